// round 2
// baseline (speedup 1.0000x reference)
#include <cuda_runtime.h>
#include <math.h>

// Problem dims (fixed)
#define Bb 64
#define Tt 128
#define Ff 2048
#define Hh 1024
#define Cc 22
#define G4 4096   // 4*H
#define NB 128    // persistent grid size (blocks) — must be <= #SMs (148)

// ---------------- scratch (device globals; no allocation allowed) ----------------
__device__ float g_enc_xw[Bb*Tt*G4];   // x @ enc_Wih^T + enc_b   [B,T,4H]
__device__ float g_dec_xw[Bb*Tt*G4];   // x @ dec_Wih[:, :F]^T + dec_b
__device__ float g_hts  [Bb*Tt*Hh];    // encoder hidden states [B,T,H]
__device__ float g_proj [Bb*Tt*Hh];    // projected enc states  [B,T,H]
__device__ float g_h [Bb*Hh];
__device__ float g_c [Bb*Hh];
__device__ float g_h2[Bb*Hh];
__device__ float g_c2[Bb*Hh];
__device__ float g_gates[Bb*G4];
__device__ float g_attn [Bb*Hh];
__device__ float g_part [4*Bb*Hh];     // split-K partials for attnp GEMM
__device__ float g_logits[Bb*Tt];

// ---------------- software grid barrier (all NB blocks participate) --------------
__device__ unsigned g_barcnt;
__device__ unsigned g_bargen;

__device__ __forceinline__ void gbar()
{
    __syncthreads();
    if (threadIdx.x == 0) {
        __threadfence();
        unsigned gen = *(volatile unsigned*)&g_bargen;
        if (atomicAdd(&g_barcnt, 1u) == NB - 1u) {
            g_barcnt = 0u;
            __threadfence();
            atomicAdd(&g_bargen, 1u);
        } else {
            while (*(volatile unsigned*)&g_bargen == gen) { }
        }
        __threadfence();
    }
    __syncthreads();
}

__device__ __forceinline__ float sigm(float x) { return 1.f / (1.f + expf(-x)); }

__device__ __forceinline__ float wred(float s)
{
#pragma unroll
    for (int o = 16; o; o >>= 1) s += __shfl_down_sync(0xffffffffu, s, o);
    return s;
}

// ---------------- shared-tile helpers (64x32 output tile, BK=16) -----------------
// As padded to 72 floats/row (288B, 16B-aligned rows -> LDS.128 for a[4])
// Ws padded to 40 floats/row (160B, 8B-aligned rows  -> LDS.64  for w[2])
__device__ __forceinline__ void load_a64(float (*As)[72], const float* A, size_t lda, int tid)
{
    int lr = tid >> 2, lc = (tid & 3) * 4;
    float4 a = *(const float4*)(A + (size_t)lr * lda + lc);
    As[lc + 0][lr] = a.x; As[lc + 1][lr] = a.y;
    As[lc + 2][lr] = a.z; As[lc + 3][lr] = a.w;
}

__device__ __forceinline__ void load_w32(float (*Ws)[40], const float* W, size_t ldw, int tid)
{
    int lr = tid >> 3, lc = (tid & 7) * 2;
    float2 w = *(const float2*)(W + (size_t)lr * ldw + lc);
    Ws[lc + 0][lr] = w.x; Ws[lc + 1][lr] = w.y;
}

__device__ __forceinline__ void tile_fma(const float (*As)[72], const float (*Ws)[40],
                                         float acc[4][2], int tx, int ty)
{
#pragma unroll
    for (int kk = 0; kk < 16; kk++) {
        float a0 = As[kk][ty * 4 + 0], a1 = As[kk][ty * 4 + 1];
        float a2 = As[kk][ty * 4 + 2], a3 = As[kk][ty * 4 + 3];
        float w0 = Ws[kk][tx * 2 + 0], w1 = Ws[kk][tx * 2 + 1];
        acc[0][0] = fmaf(a0, w0, acc[0][0]); acc[0][1] = fmaf(a0, w1, acc[0][1]);
        acc[1][0] = fmaf(a1, w0, acc[1][0]); acc[1][1] = fmaf(a1, w1, acc[1][1]);
        acc[2][0] = fmaf(a2, w0, acc[2][0]); acc[2][1] = fmaf(a2, w1, acc[2][1]);
        acc[3][0] = fmaf(a3, w0, acc[3][0]); acc[3][1] = fmaf(a3, w1, acc[3][1]);
    }
}

// ---------------- standalone tiled GEMM (64x64 tiles): C = b1+b2 + A@W^T ---------
__global__ __launch_bounds__(256)
void gemm_tn64(const float* __restrict__ A, int lda,
               const float* __restrict__ W, int ldw,
               const float* __restrict__ bias1, const float* __restrict__ bias2,
               float* __restrict__ C, int ldc, int K)
{
    __shared__ __align__(16) float As[16][72];
    __shared__ __align__(16) float Ws[16][72];

    const int tid = threadIdx.x;
    const int m0 = blockIdx.y * 64;
    const int n0 = blockIdx.x * 64;
    const int tx = tid & 15;
    const int ty = tid >> 4;

    float acc[4][4];
#pragma unroll
    for (int i = 0; i < 4; i++)
#pragma unroll
        for (int j = 0; j < 4; j++) acc[i][j] = 0.f;

    for (int k0 = 0; k0 < K; k0 += 16) {
        {
            int lr = tid >> 2, lc = (tid & 3) * 4;
            float4 a = *(const float4*)(A + (size_t)(m0 + lr) * lda + k0 + lc);
            As[lc + 0][lr] = a.x; As[lc + 1][lr] = a.y;
            As[lc + 2][lr] = a.z; As[lc + 3][lr] = a.w;
            float4 w = *(const float4*)(W + (size_t)(n0 + lr) * ldw + k0 + lc);
            Ws[lc + 0][lr] = w.x; Ws[lc + 1][lr] = w.y;
            Ws[lc + 2][lr] = w.z; Ws[lc + 3][lr] = w.w;
        }
        __syncthreads();
#pragma unroll
        for (int kk = 0; kk < 16; kk++) {
            float a[4], w[4];
#pragma unroll
            for (int i = 0; i < 4; i++) a[i] = As[kk][ty * 4 + i];
#pragma unroll
            for (int j = 0; j < 4; j++) w[j] = Ws[kk][tx * 4 + j];
#pragma unroll
            for (int i = 0; i < 4; i++)
#pragma unroll
                for (int j = 0; j < 4; j++)
                    acc[i][j] = fmaf(a[i], w[j], acc[i][j]);
        }
        __syncthreads();
    }

#pragma unroll
    for (int i = 0; i < 4; i++) {
        int m = m0 + ty * 4 + i;
#pragma unroll
        for (int j = 0; j < 4; j++) {
            int n = n0 + tx * 4 + j;
            float v = acc[i][j];
            if (bias1) v += bias1[n];
            if (bias2) v += bias2[n];
            C[(size_t)m * ldc + n] = v;
        }
    }
}

// ---------------- zero states + barrier counter ----------------
__global__ void zero_states_kernel()
{
    int idx = blockIdx.x * blockDim.x + threadIdx.x;
    if (idx < Bb * Hh) {
        g_h[idx] = 0.f; g_c[idx] = 0.f;
        g_h2[idx] = 0.f; g_c2[idx] = 0.f;
    }
    if (idx == 0) g_barcnt = 0u;
}

// ================= persistent encoder scan (NB blocks x 256 threads) =============
__global__ __launch_bounds__(256)
void enc_scan(const float* __restrict__ Whh, const float* __restrict__ xw)
{
    __shared__ __align__(16) float sm[16 * 72 + 16 * 40];
    float (*As)[72] = (float (*)[72])sm;
    float (*Ws)[40] = (float (*)[40])(sm + 16 * 72);

    const int tid = threadIdx.x;
    const int bi  = blockIdx.x;
    const int tx  = tid & 15, ty = tid >> 4;
    const int n0  = bi * 32;

    for (int t = 0; t < Tt; t++) {
        // ---- gates tile: [64, 32] = h @ Whh^T (K=1024) ----
        float acc[4][2] = {{0.f,0.f},{0.f,0.f},{0.f,0.f},{0.f,0.f}};
        for (int k0 = 0; k0 < Hh; k0 += 16) {
            load_a64(As, g_h + k0, Hh, tid);
            load_w32(Ws, Whh + (size_t)n0 * Hh + k0, Hh, tid);
            __syncthreads();
            tile_fma(As, Ws, acc, tx, ty);
            __syncthreads();
        }
#pragma unroll
        for (int i = 0; i < 4; i++) {
            int m = ty * 4 + i;
#pragma unroll
            for (int j = 0; j < 2; j++) {
                int n = n0 + tx * 2 + j;
                g_gates[(size_t)m * G4 + n] =
                    acc[i][j] + xw[((size_t)m * Tt + t) * G4 + n];
            }
        }
        gbar();

        // ---- LSTM cell pointwise: 65536 elems / 128 blocks ----
        {
            int idx = bi * 512 + tid * 2;
            int b = idx >> 10, j = idx & (Hh - 1);
            const float* g = g_gates + (size_t)b * G4 + j;
            float2 gi = *(const float2*)(g);
            float2 gf = *(const float2*)(g + Hh);
            float2 gg = *(const float2*)(g + 2 * Hh);
            float2 go = *(const float2*)(g + 3 * Hh);
            float2 cc = *(const float2*)(g_c + idx);
            float2 cn, hn;
            cn.x = sigm(gf.x) * cc.x + sigm(gi.x) * tanhf(gg.x);
            cn.y = sigm(gf.y) * cc.y + sigm(gi.y) * tanhf(gg.y);
            hn.x = sigm(go.x) * tanhf(cn.x);
            hn.y = sigm(go.y) * tanhf(cn.y);
            *(float2*)(g_c + idx) = cn;
            *(float2*)(g_h + idx) = hn;
            *(float2*)(g_hts + ((size_t)b * Tt + t) * Hh + j) = hn;
        }
        gbar();
    }
}

// ================= persistent decoder scan (NB blocks x 256 threads) =============
__global__ __launch_bounds__(256)
void dec_scan(const float* __restrict__ Wd2e, const float* __restrict__ bd2e,
              const float* __restrict__ dWih, const float* __restrict__ dWhh,
              const float* __restrict__ Wc,   const float* __restrict__ bc,
              const float* __restrict__ xw,
              float* __restrict__ scores, float* __restrict__ aw_out)
{
    __shared__ __align__(16) float sm[16 * 72 + 16 * 40];
    float (*As)[72] = (float (*)[72])sm;
    float (*Ws)[40] = (float (*)[40])(sm + 16 * 72);

    const int tid = threadIdx.x;
    const int bi  = blockIdx.x;
    const int tx  = tid & 15, ty = tid >> 4;
    const int warp = tid >> 5, lane = tid & 31;

    for (int t = 0; t < Tt; t++) {
        // ---- P0: attention logits (blocks paired: b = bi/2, half of T each) ----
        {
            int b = bi >> 1;
            int th = (bi & 1) * 64;
            float* sh = sm;  // 1024 floats
            *(float4*)(sh + tid * 4) = *(const float4*)(g_h2 + (size_t)b * Hh + tid * 4);
            __syncthreads();
#pragma unroll
            for (int ii = 0; ii < 8; ii++) {
                int tp = th + warp * 8 + ii;
                const float* pr = g_proj + ((size_t)b * Tt + tp) * Hh;
                float s = 0.f;
#pragma unroll 8
                for (int k = lane; k < Hh; k += 32) s += sh[k] * pr[k];
                s = wred(s);
                if (lane == 0) g_logits[b * Tt + tp] = s * 0.03125f;
            }
        }
        gbar();

        // ---- P1: softmax (redundant per block pair) + weighted sum halves ----
        {
            int b = bi >> 1, kh = bi & 1;
            float* sl  = sm;        // 128
            float* red = sm + 128;  // 256
            if (tid < Tt) sl[tid] = g_logits[b * Tt + tid];
            __syncthreads();
            float v = (tid < Tt) ? sl[tid] : -3.4e38f;
            red[tid] = v; __syncthreads();
            for (int s = 128; s; s >>= 1) {
                if (tid < s) red[tid] = fmaxf(red[tid], red[tid + s]);
                __syncthreads();
            }
            float mx = red[0]; __syncthreads();
            float e = (tid < Tt) ? expf(sl[tid] - mx) : 0.f;
            red[tid] = e; __syncthreads();
            for (int s = 128; s; s >>= 1) {
                if (tid < s) red[tid] += red[tid + s];
                __syncthreads();
            }
            float inv = 1.f / red[0]; __syncthreads();
            if (tid < Tt) sl[tid] = e * inv;
            __syncthreads();
            if (t == Tt - 1 && kh == 0 && tid < Tt)
                aw_out[(size_t)b * Tt + tid] = sl[tid];

            int k = kh * 512 + tid * 2;
            const float* pb = g_proj + (size_t)b * Tt * Hh + k;
            float2 a; a.x = 0.f; a.y = 0.f;
#pragma unroll 4
            for (int tp = 0; tp < Tt; tp++) {
                float2 p = *(const float2*)(pb + (size_t)tp * Hh);
                float w = sl[tp];
                a.x = fmaf(w, p.x, a.x);
                a.y = fmaf(w, p.y, a.y);
            }
            *(float2*)(g_attn + (size_t)b * Hh + k) = a;
        }
        gbar();

        // ---- P3: attnp partials: attn @ Wd2e^T, split-K x4 (deterministic) ----
        {
            int ntile = bi >> 2, ks = bi & 3;
            int n0 = ntile * 32, koff = ks * 256;
            float acc[4][2] = {{0.f,0.f},{0.f,0.f},{0.f,0.f},{0.f,0.f}};
            for (int k0 = 0; k0 < 256; k0 += 16) {
                load_a64(As, g_attn + koff + k0, Hh, tid);
                load_w32(Ws, Wd2e + (size_t)n0 * Hh + koff + k0, Hh, tid);
                __syncthreads();
                tile_fma(As, Ws, acc, tx, ty);
                __syncthreads();
            }
#pragma unroll
            for (int i = 0; i < 4; i++) {
                int m = ty * 4 + i;
#pragma unroll
                for (int j = 0; j < 2; j++) {
                    int n = n0 + tx * 2 + j;
                    g_part[((size_t)ks * Bb + m) * Hh + n] = acc[i][j];
                }
            }
        }
        gbar();

        // ---- P5: gates = dec_xw[t] + attnp @ dWih[:,F:]^T + h2 @ dWhh^T ------
        {
            int n0 = bi * 32;
            float acc[4][2] = {{0.f,0.f},{0.f,0.f},{0.f,0.f},{0.f,0.f}};
            // loop 1: A = attnp (reduce 4 partials + bias on load)
            for (int k0 = 0; k0 < Hh; k0 += 16) {
                {
                    int lr = tid >> 2, lc = (tid & 3) * 4;
                    int k = k0 + lc;
                    const float* p = g_part + (size_t)lr * Hh + k;
                    float4 a0 = *(const float4*)(p);
                    float4 a1 = *(const float4*)(p + (size_t)Bb * Hh);
                    float4 a2 = *(const float4*)(p + (size_t)2 * Bb * Hh);
                    float4 a3 = *(const float4*)(p + (size_t)3 * Bb * Hh);
                    float4 bb = *(const float4*)(bd2e + k);
                    As[lc + 0][lr] = a0.x + a1.x + a2.x + a3.x + bb.x;
                    As[lc + 1][lr] = a0.y + a1.y + a2.y + a3.y + bb.y;
                    As[lc + 2][lr] = a0.z + a1.z + a2.z + a3.z + bb.z;
                    As[lc + 3][lr] = a0.w + a1.w + a2.w + a3.w + bb.w;
                }
                load_w32(Ws, dWih + (size_t)n0 * (Ff + Hh) + Ff + k0, Ff + Hh, tid);
                __syncthreads();
                tile_fma(As, Ws, acc, tx, ty);
                __syncthreads();
            }
            // loop 2: A = h2, W = dWhh
            for (int k0 = 0; k0 < Hh; k0 += 16) {
                load_a64(As, g_h2 + k0, Hh, tid);
                load_w32(Ws, dWhh + (size_t)n0 * Hh + k0, Hh, tid);
                __syncthreads();
                tile_fma(As, Ws, acc, tx, ty);
                __syncthreads();
            }
#pragma unroll
            for (int i = 0; i < 4; i++) {
                int m = ty * 4 + i;
#pragma unroll
                for (int j = 0; j < 2; j++) {
                    int n = n0 + tx * 2 + j;
                    g_gates[(size_t)m * G4 + n] =
                        acc[i][j] + xw[((size_t)m * Tt + t) * G4 + n];
                }
            }
        }
        gbar();

        // ---- P6+P7: LSTM cell (per-batch block) + classifier fused -----------
        if (bi < Bb) {
            int b = bi;
            float* shh = sm;  // 1024
            int j = tid * 4;
            const float* g = g_gates + (size_t)b * G4 + j;
            float4 gi = *(const float4*)(g);
            float4 gf = *(const float4*)(g + Hh);
            float4 gg = *(const float4*)(g + 2 * Hh);
            float4 go = *(const float4*)(g + 3 * Hh);
            float4 cc = *(const float4*)(g_c2 + (size_t)b * Hh + j);
            float4 cn, hn;
            cn.x = sigm(gf.x) * cc.x + sigm(gi.x) * tanhf(gg.x);
            cn.y = sigm(gf.y) * cc.y + sigm(gi.y) * tanhf(gg.y);
            cn.z = sigm(gf.z) * cc.z + sigm(gi.z) * tanhf(gg.z);
            cn.w = sigm(gf.w) * cc.w + sigm(gi.w) * tanhf(gg.w);
            hn.x = sigm(go.x) * tanhf(cn.x);
            hn.y = sigm(go.y) * tanhf(cn.y);
            hn.z = sigm(go.z) * tanhf(cn.z);
            hn.w = sigm(go.w) * tanhf(cn.w);
            *(float4*)(g_c2 + (size_t)b * Hh + j) = cn;
            *(float4*)(g_h2 + (size_t)b * Hh + j) = hn;
            *(float4*)(shh + j) = hn;
            __syncthreads();
            for (int c = warp; c < Cc; c += 8) {
                const float* w = Wc + (size_t)c * Hh;
                float s = 0.f;
#pragma unroll 8
                for (int k = lane; k < Hh; k += 32) s += shh[k] * w[k];
                s = wred(s);
                if (lane == 0)
                    scores[((size_t)b * Tt + t) * Cc + c] = s + bc[c];
            }
        }
        gbar();
    }
}

// ---------------- host ----------------
extern "C" void kernel_launch(void* const* d_in, const int* in_sizes, int n_in,
                              void* d_out, int out_size)
{
    const float* x        = (const float*)d_in[0];
    const float* enc_Wih  = (const float*)d_in[1];
    const float* enc_Whh  = (const float*)d_in[2];
    const float* enc_bih  = (const float*)d_in[3];
    const float* enc_bhh  = (const float*)d_in[4];
    const float* We2d     = (const float*)d_in[5];
    const float* be2d     = (const float*)d_in[6];
    const float* Wd2e     = (const float*)d_in[7];
    const float* bd2e     = (const float*)d_in[8];
    const float* dec_Wih  = (const float*)d_in[9];
    const float* dec_Whh  = (const float*)d_in[10];
    const float* dec_bih  = (const float*)d_in[11];
    const float* dec_bhh  = (const float*)d_in[12];
    const float* Wc       = (const float*)d_in[13];
    const float* bc       = (const float*)d_in[14];

    float* out    = (float*)d_out;
    float* scores = out;                        // [B,T,C]
    float* aw_out = out + (size_t)Bb * Tt * Cc; // [B,T]

    float *enc_xw, *dec_xw, *hts, *proj;
    cudaGetSymbolAddress((void**)&enc_xw, g_enc_xw);
    cudaGetSymbolAddress((void**)&dec_xw, g_dec_xw);
    cudaGetSymbolAddress((void**)&hts,    g_hts);
    cudaGetSymbolAddress((void**)&proj,   g_proj);

    // 1) zero recurrent states + barrier counter
    zero_states_kernel<<<(Bb * Hh + 255) / 256, 256>>>();

    // 2) time-parallel input transforms (biases folded in)
    {
        dim3 grid(G4 / 64, (Bb * Tt) / 64);
        gemm_tn64<<<grid, 256>>>(x, Ff, enc_Wih, Ff, enc_bih, enc_bhh,
                                 enc_xw, G4, Ff);
        gemm_tn64<<<grid, 256>>>(x, Ff, dec_Wih, Ff + Hh, dec_bih, dec_bhh,
                                 dec_xw, G4, Ff);
    }

    // 3) encoder scan (persistent, 2 grid barriers / step)
    enc_scan<<<NB, 256>>>(enc_Whh, enc_xw);

    // 4) projection of encoder states
    {
        dim3 grid(Hh / 64, (Bb * Tt) / 64);
        gemm_tn64<<<grid, 256>>>(hts, Hh, We2d, Hh, be2d, nullptr,
                                 proj, Hh, Hh);
    }

    // 5) decoder scan with attention (persistent, 5 grid barriers / step)
    dec_scan<<<NB, 256>>>(Wd2e, bd2e, dec_Wih, dec_Whh, Wc, bc,
                          dec_xw, scores, aw_out);
}

// round 3
// speedup vs baseline: 1.6888x; 1.6888x over previous
#include <cuda_runtime.h>
#include <math.h>

// Problem dims (fixed)
#define Bb 64
#define Tt 128
#define Ff 2048
#define Hh 1024
#define Cc 22
#define G4 4096   // 4*H
#define NB 128    // persistent grid size

// ---------------- scratch (device globals) ----------------
__device__ float g_enc_xw[Bb*Tt*G4];   // x @ enc_Wih'^T + enc_b'   [B,T,4H] (gate-permuted cols)
__device__ float g_dec_xw[Bb*Tt*G4];   // x @ dec_Wih_x'^T + dec_b'
__device__ float g_hts [Bb*Tt*Hh];
__device__ float g_proj[Bb*Tt*Hh];
__device__ float g_hA[Bb*Hh], g_hB[Bb*Hh], g_c1[Bb*Hh];
__device__ float g_h2A[Bb*Hh], g_h2B[Bb*Hh], g_c2[Bb*Hh];
__device__ float g_attn[Bb*Hh];
__device__ float g_logits[Bb*Tt];
// permuted weights (row r = g*H+j  ->  p = 4*j+g)
__device__ float g_Wih_e[(size_t)G4*Ff];
__device__ float g_Wih_d[(size_t)G4*Ff];
__device__ float g_Whh_e[(size_t)G4*Hh];
__device__ float g_Wd_h [(size_t)G4*Hh];   // dec_Wih[:, F:] permuted
__device__ float g_Whh_d[(size_t)G4*Hh];
__device__ float g_Wfused[(size_t)G4*Hh];  // g_Wd_h @ Wd2e
__device__ float g_be[G4], g_bd[G4], g_bf[G4];
__device__ unsigned g_barcnt, g_bargen;

// ---------------- f32x2 packed helpers (Blackwell FFMA2) ----------------
__device__ __forceinline__ unsigned long long pk2(float x, float y)
{ unsigned long long r; asm("mov.b64 %0, {%1, %2};" : "=l"(r) : "f"(x), "f"(y)); return r; }
__device__ __forceinline__ unsigned long long ffma2(unsigned long long a, unsigned long long b, unsigned long long c)
{ unsigned long long d; asm("fma.rn.f32x2 %0, %1, %2, %3;" : "=l"(d) : "l"(a), "l"(b), "l"(c)); return d; }
__device__ __forceinline__ float2 upk(unsigned long long v)
{ float2 f; asm("mov.b64 {%0, %1}, %2;" : "=f"(f.x), "=f"(f.y) : "l"(v)); return f; }

// ---------------- grid barrier ----------------
__device__ __forceinline__ void gbar()
{
    __syncthreads();
    if (threadIdx.x == 0) {
        __threadfence();
        unsigned gen = *(volatile unsigned*)&g_bargen;
        if (atomicAdd(&g_barcnt, 1u) == NB - 1u) {
            g_barcnt = 0u;
            __threadfence();
            atomicAdd(&g_bargen, 1u);
        } else {
            while (*(volatile unsigned*)&g_bargen == gen) { }
        }
        __threadfence();
    }
    __syncthreads();
}

__device__ __forceinline__ float sigm(float x) { return 1.f / (1.f + expf(-x)); }
__device__ __forceinline__ float wred(float s)
{
#pragma unroll
    for (int o = 16; o; o >>= 1) s += __shfl_down_sync(0xffffffffu, s, o);
    return s;
}

// ================= setup kernels =================
// permute rows: dst[4j+g][0..K) = src[g*H+j][0..K)
__global__ void perm_w_kernel(float* dst, const float* src, int ldsrc, int K)
{
    int r = blockIdx.x;
    int g = r >> 10, j = r & 1023;
    int p = 4 * j + g;
    const float* s = src + (size_t)r * ldsrc;
    float*       d = dst + (size_t)p * K;
    for (int k = threadIdx.x * 4; k < K; k += blockDim.x * 4)
        *(float4*)(d + k) = *(const float4*)(s + k);
}

__global__ void perm_b_kernel(const float* ebi, const float* ebh,
                              const float* dbi, const float* dbh)
{
    int r = blockIdx.x * blockDim.x + threadIdx.x;
    if (r < G4) {
        int g = r >> 10, j = r & 1023, p = 4 * j + g;
        g_be[p] = ebi[r] + ebh[r];
        g_bd[p] = dbi[r] + dbh[r];
    }
}

// bf[p] = dot(g_Wd_h[p,:], bd2e)
__global__ void bfused_kernel(const float* __restrict__ bd2e)
{
    int p = blockIdx.x;
    const float* w = g_Wd_h + (size_t)p * Hh;
    float s = 0.f;
    for (int k = threadIdx.x; k < Hh; k += 32) s += w[k] * bd2e[k];
    s = wred(s);
    if (threadIdx.x == 0) g_bf[p] = s;
}

__global__ void zero_kernel()
{
    int i = blockIdx.x * blockDim.x + threadIdx.x;
    if (i < Bb * Hh) {
        g_hA[i] = 0.f; g_hB[i] = 0.f; g_c1[i] = 0.f;
        g_h2A[i] = 0.f; g_h2B[i] = 0.f; g_c2[i] = 0.f;
    }
    if (i == 0) g_barcnt = 0u;
}

// ================= big GEMM, 128x64 tiles, f32x2 =================
// TRANSB=true : C = A[M,K] @ B[N,K]^T (+b1+b2)
// TRANSB=false: C = A[M,K] @ B[K,N]
template<bool TRANSB>
__global__ __launch_bounds__(256)
void gemm128x64(const float* __restrict__ A, int lda,
                const float* __restrict__ B, int ldb,
                const float* __restrict__ b1, const float* __restrict__ b2,
                float* __restrict__ C, int ldc, int K)
{
    __shared__ __align__(16) float As[16][136];
    __shared__ __align__(16) float Bs[16][72];

    const int tid = threadIdx.x;
    const int m0 = blockIdx.y * 128;
    const int n0 = blockIdx.x * 64;
    const int tx = tid & 15;   // n: tx*4
    const int ty = tid >> 4;   // m: ty*8

    unsigned long long acc[4][4];
#pragma unroll
    for (int p = 0; p < 4; p++)
#pragma unroll
        for (int j = 0; j < 4; j++) acc[p][j] = 0ull;

    for (int k0 = 0; k0 < K; k0 += 16) {
        {   // A tile 128x16
            int lr = tid >> 1, lc = (tid & 1) * 8;
            const float* a = A + (size_t)(m0 + lr) * lda + k0 + lc;
            float4 v0 = *(const float4*)a;
            float4 v1 = *(const float4*)(a + 4);
            As[lc + 0][lr] = v0.x; As[lc + 1][lr] = v0.y;
            As[lc + 2][lr] = v0.z; As[lc + 3][lr] = v0.w;
            As[lc + 4][lr] = v1.x; As[lc + 5][lr] = v1.y;
            As[lc + 6][lr] = v1.z; As[lc + 7][lr] = v1.w;
        }
        if (TRANSB) {  // B rows are N: 64x16, transpose in smem
            int lr = tid >> 2, lc = (tid & 3) * 4;
            float4 w = *(const float4*)(B + (size_t)(n0 + lr) * ldb + k0 + lc);
            Bs[lc + 0][lr] = w.x; Bs[lc + 1][lr] = w.y;
            Bs[lc + 2][lr] = w.z; Bs[lc + 3][lr] = w.w;
        } else {       // B rows are K: 16x64, direct
            int kr = tid >> 4, nc = (tid & 15) * 4;
            *(float4*)&Bs[kr][nc] = *(const float4*)(B + (size_t)(k0 + kr) * ldb + n0 + nc);
        }
        __syncthreads();
#pragma unroll
        for (int kk = 0; kk < 16; kk++) {
            ulonglong2 ua = *(const ulonglong2*)(&As[kk][ty * 8]);
            ulonglong2 ub = *(const ulonglong2*)(&As[kk][ty * 8 + 4]);
            float4 w = *(const float4*)(&Bs[kk][tx * 4]);
            unsigned long long w0 = pk2(w.x, w.x), w1 = pk2(w.y, w.y);
            unsigned long long w2 = pk2(w.z, w.z), w3 = pk2(w.w, w.w);
            acc[0][0] = ffma2(ua.x, w0, acc[0][0]); acc[0][1] = ffma2(ua.x, w1, acc[0][1]);
            acc[0][2] = ffma2(ua.x, w2, acc[0][2]); acc[0][3] = ffma2(ua.x, w3, acc[0][3]);
            acc[1][0] = ffma2(ua.y, w0, acc[1][0]); acc[1][1] = ffma2(ua.y, w1, acc[1][1]);
            acc[1][2] = ffma2(ua.y, w2, acc[1][2]); acc[1][3] = ffma2(ua.y, w3, acc[1][3]);
            acc[2][0] = ffma2(ub.x, w0, acc[2][0]); acc[2][1] = ffma2(ub.x, w1, acc[2][1]);
            acc[2][2] = ffma2(ub.x, w2, acc[2][2]); acc[2][3] = ffma2(ub.x, w3, acc[2][3]);
            acc[3][0] = ffma2(ub.y, w0, acc[3][0]); acc[3][1] = ffma2(ub.y, w1, acc[3][1]);
            acc[3][2] = ffma2(ub.y, w2, acc[3][2]); acc[3][3] = ffma2(ub.y, w3, acc[3][3]);
        }
        __syncthreads();
    }

    float bb0 = 0.f, bb1 = 0.f, bb2v = 0.f, bb3 = 0.f;
    if (b1) { float4 t = *(const float4*)(b1 + n0 + tx * 4); bb0 += t.x; bb1 += t.y; bb2v += t.z; bb3 += t.w; }
    if (b2) { float4 t = *(const float4*)(b2 + n0 + tx * 4); bb0 += t.x; bb1 += t.y; bb2v += t.z; bb3 += t.w; }
#pragma unroll
    for (int p = 0; p < 4; p++) {
        float2 f0 = upk(acc[p][0]), f1 = upk(acc[p][1]);
        float2 f2 = upk(acc[p][2]), f3 = upk(acc[p][3]);
        int m = m0 + ty * 8 + 2 * p;
        *(float4*)(C + (size_t)m * ldc + n0 + tx * 4) =
            make_float4(f0.x + bb0, f1.x + bb1, f2.x + bb2v, f3.x + bb3);
        *(float4*)(C + (size_t)(m + 1) * ldc + n0 + tx * 4) =
            make_float4(f0.y + bb0, f1.y + bb1, f2.y + bb2v, f3.y + bb3);
    }
}

// ================= scan-tile helpers (64x32 tile, 256-thread group) ==============
// As group pitch 72 floats/row; Ws pitch 40
__device__ __forceinline__ void load_tiles(float* Asg, float* Wsg,
                                           const float* __restrict__ A,
                                           const float* __restrict__ W,
                                           int k, int t8)
{
    {
        int lr = t8 >> 2, lc = (t8 & 3) * 4;
        float4 a = *(const float4*)(A + (size_t)lr * Hh + k + lc);
        Asg[(lc + 0) * 72 + lr] = a.x; Asg[(lc + 1) * 72 + lr] = a.y;
        Asg[(lc + 2) * 72 + lr] = a.z; Asg[(lc + 3) * 72 + lr] = a.w;
    }
    {
        int lr = t8 >> 3, lc = (t8 & 7) * 2;
        float2 w = *(const float2*)(W + (size_t)lr * Hh + k + lc);
        Wsg[(lc + 0) * 40 + lr] = w.x; Wsg[(lc + 1) * 40 + lr] = w.y;
    }
}

__device__ __forceinline__ void fma_tile(const float* Asg, const float* Wsg,
                                         unsigned long long acc[2][2], int tx, int ty)
{
#pragma unroll
    for (int kk = 0; kk < 16; kk++) {
        ulonglong2 ua = *(const ulonglong2*)(Asg + kk * 72 + ty * 4);
        float2 w = *(const float2*)(Wsg + kk * 40 + tx * 2);
        unsigned long long w0 = pk2(w.x, w.x), w1 = pk2(w.y, w.y);
        acc[0][0] = ffma2(ua.x, w0, acc[0][0]); acc[0][1] = ffma2(ua.x, w1, acc[0][1]);
        acc[1][0] = ffma2(ua.y, w0, acc[1][0]); acc[1][1] = ffma2(ua.y, w1, acc[1][1]);
    }
}

__device__ __forceinline__ void store_partials(float* Pg, unsigned long long acc[2][2],
                                               int tx, int ty)
{
#pragma unroll
    for (int p = 0; p < 2; p++) {
        float2 c0 = upk(acc[p][0]), c1 = upk(acc[p][1]);
        int m = ty * 4 + 2 * p;
        Pg[m * 32 + tx * 2 + 0] = c0.x; Pg[m * 32 + tx * 2 + 1] = c1.x;
        Pg[(m + 1) * 32 + tx * 2 + 0] = c0.y; Pg[(m + 1) * 32 + tx * 2 + 1] = c1.y;
    }
}

// ================= persistent encoder scan: 1 barrier/step ======================
__global__ __launch_bounds__(512)
void enc_scan()
{
    __shared__ __align__(16) float sm[7680];
    const int tid = threadIdx.x, bi = blockIdx.x;
    const int g = tid >> 8, t8 = tid & 255;
    const int tx = t8 & 15, ty = t8 >> 4;
    const int n0 = bi * 32;
    float* Asg = sm + g * 1152;
    float* Wsg = sm + 2304 + g * 640;
    float* P   = sm + 3584;          // [2][64][32]
    const float* W = g_Whh_e + (size_t)n0 * Hh + g * 512;

    for (int t = 0; t < Tt; t++) {
        const float* hcur = (t & 1) ? g_hB : g_hA;
        float*       hnxt = (t & 1) ? g_hA : g_hB;
        const float* Ab = hcur + g * 512;

        unsigned long long acc[2][2] = {{0ull, 0ull}, {0ull, 0ull}};
        for (int k0 = 0; k0 < 512; k0 += 16) {
            load_tiles(Asg, Wsg, Ab, W, k0, t8);
            __syncthreads();
            fma_tile(Asg, Wsg, acc, tx, ty);
            __syncthreads();
        }
        store_partials(P + g * 2048, acc, tx, ty);
        __syncthreads();

        {   // fused LSTM cell: thread -> (b, jj)
            int b = tid >> 3, jj = tid & 7, j = bi * 8 + jj;
            float4 x4 = *(const float4*)(g_enc_xw + ((size_t)b * Tt + t) * G4 + n0 + 4 * jj);
            int base = b * 32 + 4 * jj;
            float vi = P[base + 0] + P[2048 + base + 0] + x4.x;
            float vf = P[base + 1] + P[2048 + base + 1] + x4.y;
            float vg = P[base + 2] + P[2048 + base + 2] + x4.z;
            float vo = P[base + 3] + P[2048 + base + 3] + x4.w;
            float cn = sigm(vf) * g_c1[b * Hh + j] + sigm(vi) * tanhf(vg);
            float hn = sigm(vo) * tanhf(cn);
            g_c1[b * Hh + j] = cn;
            hnxt[b * Hh + j] = hn;
            g_hts[((size_t)b * Tt + t) * Hh + j] = hn;
        }
        gbar();
    }
}

// ================= persistent decoder scan: 3 barriers/step =====================
__global__ __launch_bounds__(512)
void dec_scan(const float* __restrict__ Wc, const float* __restrict__ bc,
              float* __restrict__ scores, float* __restrict__ aw_out)
{
    __shared__ __align__(16) float sm[7680];
    const int tid = threadIdx.x, bi = blockIdx.x;
    const int warp = tid >> 5, lane = tid & 31;
    const int g = tid >> 8, t8 = tid & 255;
    const int tx = t8 & 15, ty = t8 >> 4;
    const int b2 = bi >> 1;
    const int n0 = bi * 32;

    for (int t = 0; t < Tt; t++) {
        const float* h2cur = (t & 1) ? g_h2B : g_h2A;
        float*       h2nxt = (t & 1) ? g_h2A : g_h2B;

        // ---- A: logits + classifier(t-1) ----
        {
            float* sh = sm;
            *(float2*)(sh + tid * 2) = *(const float2*)(h2cur + (size_t)b2 * Hh + tid * 2);
            __syncthreads();
            int th = (bi & 1) * 64;
#pragma unroll
            for (int ii = 0; ii < 4; ii++) {
                int tp = th + ii * 16 + warp;
                const float* pr = g_proj + ((size_t)b2 * Tt + tp) * Hh;
                float s = 0.f;
#pragma unroll 8
                for (int k = lane; k < Hh; k += 32) s += sh[k] * pr[k];
                s = wred(s);
                if (lane == 0) g_logits[b2 * Tt + tp] = s * 0.03125f;
            }
            if (t > 0 && warp < 11) {
                int c = (bi & 1) * 11 + warp;
                const float* w = Wc + (size_t)c * Hh;
                float s = 0.f;
#pragma unroll 8
                for (int k = lane; k < Hh; k += 32) s += sh[k] * w[k];
                s = wred(s);
                if (lane == 0)
                    scores[((size_t)b2 * Tt + (t - 1)) * Cc + c] = s + bc[c];
            }
        }
        gbar();

        // ---- B: softmax + attn context ----
        {
            float* sl = sm;          // 128
            float* red = sm + 128;   // 128
            if (tid < 128) { float v = g_logits[b2 * Tt + tid]; sl[tid] = v; red[tid] = v; }
            __syncthreads();
            for (int s = 64; s; s >>= 1) {
                if (tid < s) red[tid] = fmaxf(red[tid], red[tid + s]);
                __syncthreads();
            }
            float mx = red[0]; __syncthreads();
            float e = 0.f;
            if (tid < 128) { e = expf(sl[tid] - mx); red[tid] = e; }
            __syncthreads();
            for (int s = 64; s; s >>= 1) {
                if (tid < s) red[tid] += red[tid + s];
                __syncthreads();
            }
            float inv = 1.f / red[0]; __syncthreads();
            if (tid < 128) sl[tid] = e * inv;
            __syncthreads();
            if (t == Tt - 1 && (bi & 1) == 0 && tid < 128)
                aw_out[(size_t)b2 * Tt + tid] = sl[tid];

            int k = (bi & 1) * 512 + tid;
            const float* pb = g_proj + (size_t)b2 * Tt * Hh + k;
            float a = 0.f;
#pragma unroll 4
            for (int tp = 0; tp < Tt; tp++) a = fmaf(sl[tp], pb[(size_t)tp * Hh], a);
            g_attn[(size_t)b2 * Hh + k] = a;
        }
        gbar();

        // ---- C: gates = xw[t] + bf + attn@Wfused^T + h2@Whh_d^T, fused cell ----
        {
            float* Asg = sm + g * 1152;
            float* Wsg = sm + 2304 + g * 640;
            float* P   = sm + 3584;
            const float* Ab = g ? h2cur : g_attn;
            const float* W  = (g ? g_Whh_d : g_Wfused) + (size_t)n0 * Hh;

            unsigned long long acc[2][2] = {{0ull, 0ull}, {0ull, 0ull}};
            for (int k0 = 0; k0 < Hh; k0 += 16) {
                load_tiles(Asg, Wsg, Ab, W, k0, t8);
                __syncthreads();
                fma_tile(Asg, Wsg, acc, tx, ty);
                __syncthreads();
            }
            store_partials(P + g * 2048, acc, tx, ty);
            __syncthreads();

            int b = tid >> 3, jj = tid & 7, j = bi * 8 + jj;
            float4 x4 = *(const float4*)(g_dec_xw + ((size_t)b * Tt + t) * G4 + n0 + 4 * jj);
            float4 bf4 = *(const float4*)(g_bf + n0 + 4 * jj);
            int base = b * 32 + 4 * jj;
            float vi = P[base + 0] + P[2048 + base + 0] + x4.x + bf4.x;
            float vf = P[base + 1] + P[2048 + base + 1] + x4.y + bf4.y;
            float vg = P[base + 2] + P[2048 + base + 2] + x4.z + bf4.z;
            float vo = P[base + 3] + P[2048 + base + 3] + x4.w + bf4.w;
            float cn = sigm(vf) * g_c2[b * Hh + j] + sigm(vi) * tanhf(vg);
            float hn = sigm(vo) * tanhf(cn);
            g_c2[b * Hh + j] = cn;
            h2nxt[b * Hh + j] = hn;
        }
        gbar();
    }

    // ---- final classifier for t = Tt-1 (h2 in buffer A after t=127) ----
    {
        float* sh = sm;
        *(float2*)(sh + tid * 2) = *(const float2*)(g_h2A + (size_t)b2 * Hh + tid * 2);
        __syncthreads();
        if (warp < 11) {
            int c = (bi & 1) * 11 + warp;
            const float* w = Wc + (size_t)c * Hh;
            float s = 0.f;
#pragma unroll 8
            for (int k = lane; k < Hh; k += 32) s += sh[k] * w[k];
            s = wred(s);
            if (lane == 0)
                scores[((size_t)b2 * Tt + (Tt - 1)) * Cc + c] = s + bc[c];
        }
    }
}

// ---------------- host ----------------
extern "C" void kernel_launch(void* const* d_in, const int* in_sizes, int n_in,
                              void* d_out, int out_size)
{
    const float* x        = (const float*)d_in[0];
    const float* enc_Wih  = (const float*)d_in[1];
    const float* enc_Whh  = (const float*)d_in[2];
    const float* enc_bih  = (const float*)d_in[3];
    const float* enc_bhh  = (const float*)d_in[4];
    const float* We2d     = (const float*)d_in[5];
    const float* be2d     = (const float*)d_in[6];
    const float* Wd2e     = (const float*)d_in[7];
    const float* bd2e     = (const float*)d_in[8];
    const float* dec_Wih  = (const float*)d_in[9];
    const float* dec_Whh  = (const float*)d_in[10];
    const float* dec_bih  = (const float*)d_in[11];
    const float* dec_bhh  = (const float*)d_in[12];
    const float* Wc       = (const float*)d_in[13];
    const float* bc       = (const float*)d_in[14];

    float* out    = (float*)d_out;
    float* scores = out;                        // [B,T,C]
    float* aw_out = out + (size_t)Bb * Tt * Cc; // [B,T]

    float *enc_xw_p, *dec_xw_p, *hts_p, *proj_p, *Wih_e_p, *Wih_d_p, *Whh_e_p,
          *Wd_h_p, *Whh_d_p, *Wfused_p, *be_p, *bd_p;
    cudaGetSymbolAddress((void**)&enc_xw_p, g_enc_xw);
    cudaGetSymbolAddress((void**)&dec_xw_p, g_dec_xw);
    cudaGetSymbolAddress((void**)&hts_p,    g_hts);
    cudaGetSymbolAddress((void**)&proj_p,   g_proj);
    cudaGetSymbolAddress((void**)&Wih_e_p,  g_Wih_e);
    cudaGetSymbolAddress((void**)&Wih_d_p,  g_Wih_d);
    cudaGetSymbolAddress((void**)&Whh_e_p,  g_Whh_e);
    cudaGetSymbolAddress((void**)&Wd_h_p,   g_Wd_h);
    cudaGetSymbolAddress((void**)&Whh_d_p,  g_Whh_d);
    cudaGetSymbolAddress((void**)&Wfused_p, g_Wfused);
    cudaGetSymbolAddress((void**)&be_p,     g_be);
    cudaGetSymbolAddress((void**)&bd_p,     g_bd);

    // 1) zero states + barrier
    zero_kernel<<<(Bb * Hh + 255) / 256, 256>>>();

    // 2) permute weights into gate-interleaved layout
    perm_w_kernel<<<G4, 256>>>(Wih_e_p, enc_Wih, Ff, Ff);
    perm_w_kernel<<<G4, 256>>>(Wih_d_p, dec_Wih, Ff + Hh, Ff);
    perm_w_kernel<<<G4, 256>>>(Whh_e_p, enc_Whh, Hh, Hh);
    perm_w_kernel<<<G4, 256>>>(Wd_h_p,  dec_Wih + Ff, Ff + Hh, Hh);
    perm_w_kernel<<<G4, 256>>>(Whh_d_p, dec_Whh, Hh, Hh);
    perm_b_kernel<<<16, 256>>>(enc_bih, enc_bhh, dec_bih, dec_bhh);
    bfused_kernel<<<G4, 32>>>(bd2e);

    // 3) Wfused = Wd_h_p @ Wd2e   (A@B, no transpose)
    {
        dim3 grid(Hh / 64, G4 / 128);
        gemm128x64<false><<<grid, 256>>>(Wd_h_p, Hh, Wd2e, Hh,
                                         nullptr, nullptr, Wfused_p, Hh, Hh);
    }

    // 4) time-parallel input transforms (permuted cols, biases folded)
    {
        dim3 grid(G4 / 64, (Bb * Tt) / 128);
        gemm128x64<true><<<grid, 256>>>(x, Ff, Wih_e_p, Ff, be_p, nullptr,
                                        enc_xw_p, G4, Ff);
        gemm128x64<true><<<grid, 256>>>(x, Ff, Wih_d_p, Ff, bd_p, nullptr,
                                        dec_xw_p, G4, Ff);
    }

    // 5) encoder scan (1 barrier/step)
    enc_scan<<<NB, 512>>>();

    // 6) projection of encoder states
    {
        dim3 grid(Hh / 64, (Bb * Tt) / 128);
        gemm128x64<true><<<grid, 256>>>(hts_p, Hh, We2d, Hh, be2d, nullptr,
                                        proj_p, Hh, Hh);
    }

    // 7) decoder scan (3 barriers/step)
    dec_scan<<<NB, 512>>>(Wc, bc, scores, aw_out);
}

// round 7
// speedup vs baseline: 2.0106x; 1.1905x over previous
#include <cuda_runtime.h>
#include <cuda_bf16.h>
#include <math.h>
#include <stdint.h>

// Problem dims (fixed)
#define Bb 64
#define Tt 128
#define Ff 2048
#define Hh 1024
#define Cc 22
#define G4 4096   // 4*H
#define NB 128    // persistent grid size
#define MT 8192   // Bb*Tt

// ---------------- scratch (device globals) ----------------
__device__ float g_enc_xw[(size_t)MT*G4];
__device__ float g_dec_xw[(size_t)MT*G4];
__device__ float g_hts [(size_t)MT*Hh];
__device__ float g_proj[(size_t)MT*Hh];
__device__ float g_hA[Bb*Hh], g_hB[Bb*Hh], g_c1[Bb*Hh];
__device__ float g_h2A[Bb*Hh], g_h2B[Bb*Hh], g_c2[Bb*Hh];
__device__ float g_attn[Bb*Hh];
__device__ float g_logits[Bb*Tt];
// permuted fp32 weights (row r = g*H+j  ->  p = 4*j+g)
__device__ float g_Wih_e[(size_t)G4*Ff];
__device__ float g_Wih_d[(size_t)G4*Ff];
__device__ float g_Whh_e[(size_t)G4*Hh];
__device__ float g_Wd_h [(size_t)G4*Hh];
__device__ float g_Whh_d[(size_t)G4*Hh];
__device__ float g_Wfused[(size_t)G4*Hh];
__device__ float g_be[G4], g_bd[G4], g_bf[G4];
__device__ unsigned g_barcnt, g_bargen;
// bf16 hi/lo operands for tensor-core GEMMs
__device__ __nv_bfloat16 g_xhi[(size_t)MT*Ff],  g_xlo[(size_t)MT*Ff];
__device__ __nv_bfloat16 g_Wehi[(size_t)G4*Ff], g_Welo[(size_t)G4*Ff];
__device__ __nv_bfloat16 g_Wdhi[(size_t)G4*Ff], g_Wdlo[(size_t)G4*Ff];
__device__ __nv_bfloat16 g_htshi[(size_t)MT*Hh], g_htslo[(size_t)MT*Hh];
__device__ __nv_bfloat16 g_We2dhi[(size_t)Hh*Hh], g_We2dlo[(size_t)Hh*Hh];

// ---------------- f32x2 packed helpers (for scan GEMMs) ----------------
__device__ __forceinline__ unsigned long long pk2(float x, float y)
{ unsigned long long r; asm("mov.b64 %0, {%1, %2};" : "=l"(r) : "f"(x), "f"(y)); return r; }
__device__ __forceinline__ unsigned long long ffma2(unsigned long long a, unsigned long long b, unsigned long long c)
{ unsigned long long d; asm("fma.rn.f32x2 %0, %1, %2, %3;" : "=l"(d) : "l"(a), "l"(b), "l"(c)); return d; }
__device__ __forceinline__ float2 upk(unsigned long long v)
{ float2 f; asm("mov.b64 {%0, %1}, %2;" : "=f"(f.x), "=f"(f.y) : "l"(v)); return f; }

__device__ __forceinline__ uint32_t smem_u32(const void* p)
{
    uint32_t a;
    asm("{ .reg .u64 t; cvta.to.shared.u64 t, %1; cvt.u32.u64 %0, t; }" : "=r"(a) : "l"(p));
    return a;
}

// ---------------- mma.sync helpers (sm_80+ portable) ----------------
__device__ __forceinline__ void ldmx4(uint32_t* r, uint32_t addr)
{
    asm volatile("ldmatrix.sync.aligned.m8n8.x4.shared.b16 {%0,%1,%2,%3}, [%4];"
        : "=r"(r[0]), "=r"(r[1]), "=r"(r[2]), "=r"(r[3]) : "r"(addr));
}
__device__ __forceinline__ void mma16816(float* c, const uint32_t* a, uint32_t b0, uint32_t b1)
{
    asm volatile(
        "mma.sync.aligned.m16n8k16.row.col.f32.bf16.bf16.f32 "
        "{%0,%1,%2,%3}, {%4,%5,%6,%7}, {%8,%9}, {%0,%1,%2,%3};"
        : "+f"(c[0]), "+f"(c[1]), "+f"(c[2]), "+f"(c[3])
        : "r"(a[0]), "r"(a[1]), "r"(a[2]), "r"(a[3]), "r"(b0), "r"(b1));
}
__device__ __forceinline__ void cpa16(uint32_t d, const void* s)
{
    asm volatile("cp.async.cg.shared.global [%0], [%1], 16;" :: "r"(d), "l"(s));
}

// ---------------- grid barrier ----------------
__device__ __forceinline__ void gbar()
{
    __syncthreads();
    if (threadIdx.x == 0) {
        __threadfence();
        unsigned gen = *(volatile unsigned*)&g_bargen;
        if (atomicAdd(&g_barcnt, 1u) == NB - 1u) {
            g_barcnt = 0u;
            __threadfence();
            atomicAdd(&g_bargen, 1u);
        } else {
            while (*(volatile unsigned*)&g_bargen == gen) { }
        }
        __threadfence();
    }
    __syncthreads();
}

__device__ __forceinline__ float sigm(float x) { return 1.f / (1.f + expf(-x)); }
__device__ __forceinline__ float wred(float s)
{
#pragma unroll
    for (int o = 16; o; o >>= 1) s += __shfl_down_sync(0xffffffffu, s, o);
    return s;
}

// ================= setup kernels =================
__global__ void perm_w_kernel(float* dst, const float* src, int ldsrc, int K)
{
    int r = blockIdx.x;
    int g = r >> 10, j = r & 1023;
    int p = 4 * j + g;
    const float* s = src + (size_t)r * ldsrc;
    float*       d = dst + (size_t)p * K;
    for (int k = threadIdx.x * 4; k < K; k += blockDim.x * 4)
        *(float4*)(d + k) = *(const float4*)(s + k);
}

__global__ void perm_b_kernel(const float* ebi, const float* ebh,
                              const float* dbi, const float* dbh)
{
    int r = blockIdx.x * blockDim.x + threadIdx.x;
    if (r < G4) {
        int g = r >> 10, j = r & 1023, p = 4 * j + g;
        g_be[p] = ebi[r] + ebh[r];
        g_bd[p] = dbi[r] + dbh[r];
    }
}

__global__ void bfused_kernel(const float* __restrict__ bd2e)
{
    int p = blockIdx.x;
    const float* w = g_Wd_h + (size_t)p * Hh;
    float s = 0.f;
    for (int k = threadIdx.x; k < Hh; k += 32) s += w[k] * bd2e[k];
    s = wred(s);
    if (threadIdx.x == 0) g_bf[p] = s;
}

__global__ void zero_kernel()
{
    int i = blockIdx.x * blockDim.x + threadIdx.x;
    if (i < Bb * Hh) {
        g_hA[i] = 0.f; g_hB[i] = 0.f; g_c1[i] = 0.f;
        g_h2A[i] = 0.f; g_h2B[i] = 0.f; g_c2[i] = 0.f;
    }
    if (i == 0) g_barcnt = 0u;
}

// fp32 -> bf16 hi + bf16 lo (lo = bf16(x - hi))
__global__ void conv_hilo(const float* __restrict__ in, __nv_bfloat16* __restrict__ hi,
                          __nv_bfloat16* __restrict__ lo, int n4)
{
    int i = blockIdx.x * blockDim.x + threadIdx.x;
    if (i < n4) {
        float4 v = ((const float4*)in)[i];
        __nv_bfloat162 h01, h23, l01, l23;
        h01.x = __float2bfloat16(v.x); h01.y = __float2bfloat16(v.y);
        h23.x = __float2bfloat16(v.z); h23.y = __float2bfloat16(v.w);
        l01.x = __float2bfloat16(v.x - __bfloat162float(h01.x));
        l01.y = __float2bfloat16(v.y - __bfloat162float(h01.y));
        l23.x = __float2bfloat16(v.z - __bfloat162float(h23.x));
        l23.y = __float2bfloat16(v.w - __bfloat162float(h23.y));
        ((__nv_bfloat162*)hi)[i * 2]     = h01;
        ((__nv_bfloat162*)hi)[i * 2 + 1] = h23;
        ((__nv_bfloat162*)lo)[i * 2]     = l01;
        ((__nv_bfloat162*)lo)[i * 2 + 1] = l23;
    }
}

// ================= mma.sync bf16 split-precision GEMM ============================
// C[M,N] = (Ahi+Alo)[M,K] @ (Bhi+Blo)[N,K]^T + bias   (hi*hi + hi*lo + lo*hi)
// CTA tile 128x64, BK=32, 8 warps (4 M x 2 N), warp tile 32x32.
// smem rows padded to 40 bf16 (80B stride -> conflict-free ldmatrix).
// B stored [n][k] row-major -> NON-transposed ldmatrix gives the .col B fragment.
#define PADE 40
#define ST_A   (128 * PADE * 2)                 // 10240 B (one of hi/lo)
#define ST_B   (64 * PADE * 2)                  // 5120 B
#define STAGE  (2 * ST_A + 2 * ST_B)            // 30720 B
#define MM_SMEM (2 * STAGE)                     // 61440 B

__global__ __launch_bounds__(256)
void mma_gemm(const __nv_bfloat16* __restrict__ Ahi, const __nv_bfloat16* __restrict__ Alo,
              const __nv_bfloat16* __restrict__ Bhi, const __nv_bfloat16* __restrict__ Blo,
              const float* __restrict__ bias, float* __restrict__ C, int ldc, int K)
{
    extern __shared__ char smem[];
    const uint32_t sb = smem_u32(smem);
    const int tid = threadIdx.x;
    const int wid = tid >> 5, lane = tid & 31;
    const int wm = wid & 3, wn = wid >> 2;     // warp tile origin (wm*32, wn*32)
    const int m0 = blockIdx.y * 128, n0 = blockIdx.x * 64;

    float acc[2][4][4];
#pragma unroll
    for (int i = 0; i < 2; i++)
#pragma unroll
        for (int j = 0; j < 4; j++)
#pragma unroll
            for (int q = 0; q < 4; q++) acc[i][j][q] = 0.f;

    // per-thread load slots
    const int arow = tid >> 2, aseg = tid & 3;     // A: rows 0-63 (+64), 4 segs
    const int brow = tid >> 2, bseg = tid & 3;     // B: rows 0-63

    const int S = K >> 5;

    // ldmatrix per-lane addresses (relative to stage base), constant across stages
    const int lmat = lane >> 3, lr = lane & 7;
    // A frag: row = wm*32 + mf*16 + (lmat&1)*8 + lr ; col = kk + (lmat>>1)*8
    const uint32_t a_off0 = (uint32_t)(((wm * 32 + (lmat & 1) * 8 + lr) * PADE + (lmat >> 1) * 8) * 2);
    // B frag: row(n) = wn*32 + nf2*16 + (lmat&1)*8 + lr ; col = kk + (lmat>>1)*8
    const uint32_t b_off0 = (uint32_t)(((wn * 32 + (lmat & 1) * 8 + lr) * PADE + (lmat >> 1) * 8) * 2);

#define LOAD_STAGE(buf, kb)                                                        \
    do {                                                                           \
        uint32_t st = sb + (buf) * STAGE;                                          \
        const __nv_bfloat16* gAh = Ahi + (size_t)(m0 + arow) * K + (kb) + aseg * 8;\
        const __nv_bfloat16* gAl = Alo + (size_t)(m0 + arow) * K + (kb) + aseg * 8;\
        uint32_t dA = st + (arow * PADE + aseg * 8) * 2;                           \
        cpa16(dA, gAh);                                                            \
        cpa16(dA + ST_A, gAl);                                                     \
        cpa16(dA + 64 * PADE * 2, gAh + (size_t)64 * K);                           \
        cpa16(dA + ST_A + 64 * PADE * 2, gAl + (size_t)64 * K);                    \
        const __nv_bfloat16* gBh = Bhi + (size_t)(n0 + brow) * K + (kb) + bseg * 8;\
        const __nv_bfloat16* gBl = Blo + (size_t)(n0 + brow) * K + (kb) + bseg * 8;\
        uint32_t dB = st + 2 * ST_A + (brow * PADE + bseg * 8) * 2;                \
        cpa16(dB, gBh);                                                            \
        cpa16(dB + ST_B, gBl);                                                     \
    } while (0)

    LOAD_STAGE(0, 0);
    asm volatile("cp.async.commit_group;");

    for (int s = 0; s < S; s++) {
        if (s + 1 < S) {
            LOAD_STAGE((s + 1) & 1, (s + 1) * 32);
            asm volatile("cp.async.commit_group;");
            asm volatile("cp.async.wait_group 1;");
        } else {
            asm volatile("cp.async.wait_group 0;");
        }
        __syncthreads();

        const uint32_t st = sb + (s & 1) * STAGE;
#pragma unroll
        for (int kk = 0; kk < 2; kk++) {       // two k16 steps
            const uint32_t kadd = (uint32_t)(kk * 16 * 2);
            uint32_t ah[2][4], al[2][4];
#pragma unroll
            for (int mf = 0; mf < 2; mf++) {
                uint32_t aaddr = st + a_off0 + (uint32_t)(mf * 16 * PADE * 2) + kadd;
                ldmx4(ah[mf], aaddr);
                ldmx4(al[mf], aaddr + ST_A);
            }
            uint32_t bh[2][4], bl[2][4];
#pragma unroll
            for (int nf2 = 0; nf2 < 2; nf2++) {
                uint32_t baddr = st + 2 * ST_A + b_off0 + (uint32_t)(nf2 * 16 * PADE * 2) + kadd;
                ldmx4(bh[nf2], baddr);
                ldmx4(bl[nf2], baddr + ST_B);
            }
#pragma unroll
            for (int mf = 0; mf < 2; mf++)
#pragma unroll
                for (int nf2 = 0; nf2 < 2; nf2++) {
                    // n-frag A (cols nf2*16 .. +7): k0 tile reg [0], k8 tile reg [2]
                    mma16816(acc[mf][nf2 * 2 + 0], ah[mf], bh[nf2][0], bh[nf2][2]);
                    mma16816(acc[mf][nf2 * 2 + 0], ah[mf], bl[nf2][0], bl[nf2][2]);
                    mma16816(acc[mf][nf2 * 2 + 0], al[mf], bh[nf2][0], bh[nf2][2]);
                    // n-frag B (cols +8 .. +15): regs [1],[3]
                    mma16816(acc[mf][nf2 * 2 + 1], ah[mf], bh[nf2][1], bh[nf2][3]);
                    mma16816(acc[mf][nf2 * 2 + 1], ah[mf], bl[nf2][1], bl[nf2][3]);
                    mma16816(acc[mf][nf2 * 2 + 1], al[mf], bh[nf2][1], bh[nf2][3]);
                }
        }
        __syncthreads();
    }

    // epilogue: write + bias
    const int mrow = m0 + wm * 32 + (lane >> 2);
    const int ncol = n0 + wn * 32 + (lane & 3) * 2;
#pragma unroll
    for (int mf = 0; mf < 2; mf++)
#pragma unroll
        for (int nf = 0; nf < 4; nf++) {
            int r = mrow + mf * 16;
            int c = ncol + nf * 8;
            float2 b2 = *(const float2*)(bias + c);
            *(float2*)(C + (size_t)r * ldc + c) =
                make_float2(acc[mf][nf][0] + b2.x, acc[mf][nf][1] + b2.y);
            *(float2*)(C + (size_t)(r + 8) * ldc + c) =
                make_float2(acc[mf][nf][2] + b2.x, acc[mf][nf][3] + b2.y);
        }
#undef LOAD_STAGE
}

// ================= SIMT GEMM (kept only for Wfused = Wd_h' @ Wd2e) ==============
__global__ __launch_bounds__(256)
void gemm128x64_nn(const float* __restrict__ A, int lda,
                   const float* __restrict__ B, int ldb,
                   float* __restrict__ C, int ldc, int K)
{
    __shared__ __align__(16) float As[16][136];
    __shared__ __align__(16) float Bs[16][72];

    const int tid = threadIdx.x;
    const int m0 = blockIdx.y * 128;
    const int n0 = blockIdx.x * 64;
    const int tx = tid & 15;
    const int ty = tid >> 4;

    unsigned long long acc[4][4];
#pragma unroll
    for (int p = 0; p < 4; p++)
#pragma unroll
        for (int j = 0; j < 4; j++) acc[p][j] = 0ull;

    for (int k0 = 0; k0 < K; k0 += 16) {
        {
            int lr = tid >> 1, lc = (tid & 1) * 8;
            const float* a = A + (size_t)(m0 + lr) * lda + k0 + lc;
            float4 v0 = *(const float4*)a;
            float4 v1 = *(const float4*)(a + 4);
            As[lc + 0][lr] = v0.x; As[lc + 1][lr] = v0.y;
            As[lc + 2][lr] = v0.z; As[lc + 3][lr] = v0.w;
            As[lc + 4][lr] = v1.x; As[lc + 5][lr] = v1.y;
            As[lc + 6][lr] = v1.z; As[lc + 7][lr] = v1.w;
        }
        {
            int kr = tid >> 4, nc = (tid & 15) * 4;
            *(float4*)&Bs[kr][nc] = *(const float4*)(B + (size_t)(k0 + kr) * ldb + n0 + nc);
        }
        __syncthreads();
#pragma unroll
        for (int kk = 0; kk < 16; kk++) {
            ulonglong2 ua = *(const ulonglong2*)(&As[kk][ty * 8]);
            ulonglong2 ub = *(const ulonglong2*)(&As[kk][ty * 8 + 4]);
            float4 w = *(const float4*)(&Bs[kk][tx * 4]);
            unsigned long long w0 = pk2(w.x, w.x), w1 = pk2(w.y, w.y);
            unsigned long long w2 = pk2(w.z, w.z), w3 = pk2(w.w, w.w);
            acc[0][0] = ffma2(ua.x, w0, acc[0][0]); acc[0][1] = ffma2(ua.x, w1, acc[0][1]);
            acc[0][2] = ffma2(ua.x, w2, acc[0][2]); acc[0][3] = ffma2(ua.x, w3, acc[0][3]);
            acc[1][0] = ffma2(ua.y, w0, acc[1][0]); acc[1][1] = ffma2(ua.y, w1, acc[1][1]);
            acc[1][2] = ffma2(ua.y, w2, acc[1][2]); acc[1][3] = ffma2(ua.y, w3, acc[1][3]);
            acc[2][0] = ffma2(ub.x, w0, acc[2][0]); acc[2][1] = ffma2(ub.x, w1, acc[2][1]);
            acc[2][2] = ffma2(ub.x, w2, acc[2][2]); acc[2][3] = ffma2(ub.x, w3, acc[2][3]);
            acc[3][0] = ffma2(ub.y, w0, acc[3][0]); acc[3][1] = ffma2(ub.y, w1, acc[3][1]);
            acc[3][2] = ffma2(ub.y, w2, acc[3][2]); acc[3][3] = ffma2(ub.y, w3, acc[3][3]);
        }
        __syncthreads();
    }

#pragma unroll
    for (int p = 0; p < 4; p++) {
        float2 f0 = upk(acc[p][0]), f1 = upk(acc[p][1]);
        float2 f2 = upk(acc[p][2]), f3 = upk(acc[p][3]);
        int m = m0 + ty * 8 + 2 * p;
        *(float4*)(C + (size_t)m * ldc + n0 + tx * 4) = make_float4(f0.x, f1.x, f2.x, f3.x);
        *(float4*)(C + (size_t)(m + 1) * ldc + n0 + tx * 4) = make_float4(f0.y, f1.y, f2.y, f3.y);
    }
}

// ================= scan-tile helpers (64x32 tile, 256-thread group) ==============
__device__ __forceinline__ void load_tiles(float* Asg, float* Wsg,
                                           const float* __restrict__ A,
                                           const float* __restrict__ W,
                                           int k, int t8)
{
    {
        int lr = t8 >> 2, lc = (t8 & 3) * 4;
        float4 a = *(const float4*)(A + (size_t)lr * Hh + k + lc);
        Asg[(lc + 0) * 72 + lr] = a.x; Asg[(lc + 1) * 72 + lr] = a.y;
        Asg[(lc + 2) * 72 + lr] = a.z; Asg[(lc + 3) * 72 + lr] = a.w;
    }
    {
        int lr = t8 >> 3, lc = (t8 & 7) * 2;
        float2 w = *(const float2*)(W + (size_t)lr * Hh + k + lc);
        Wsg[(lc + 0) * 40 + lr] = w.x; Wsg[(lc + 1) * 40 + lr] = w.y;
    }
}

__device__ __forceinline__ void fma_tile(const float* Asg, const float* Wsg,
                                         unsigned long long acc[2][2], int tx, int ty)
{
#pragma unroll
    for (int kk = 0; kk < 16; kk++) {
        ulonglong2 ua = *(const ulonglong2*)(Asg + kk * 72 + ty * 4);
        float2 w = *(const float2*)(Wsg + kk * 40 + tx * 2);
        unsigned long long w0 = pk2(w.x, w.x), w1 = pk2(w.y, w.y);
        acc[0][0] = ffma2(ua.x, w0, acc[0][0]); acc[0][1] = ffma2(ua.x, w1, acc[0][1]);
        acc[1][0] = ffma2(ua.y, w0, acc[1][0]); acc[1][1] = ffma2(ua.y, w1, acc[1][1]);
    }
}

__device__ __forceinline__ void store_partials(float* Pg, unsigned long long acc[2][2],
                                               int tx, int ty)
{
#pragma unroll
    for (int p = 0; p < 2; p++) {
        float2 c0 = upk(acc[p][0]), c1 = upk(acc[p][1]);
        int m = ty * 4 + 2 * p;
        Pg[m * 32 + tx * 2 + 0] = c0.x; Pg[m * 32 + tx * 2 + 1] = c1.x;
        Pg[(m + 1) * 32 + tx * 2 + 0] = c0.y; Pg[(m + 1) * 32 + tx * 2 + 1] = c1.y;
    }
}

// ================= persistent encoder scan: 1 barrier/step ======================
__global__ __launch_bounds__(512)
void enc_scan()
{
    __shared__ __align__(16) float sm[7680];
    const int tid = threadIdx.x, bi = blockIdx.x;
    const int g = tid >> 8, t8 = tid & 255;
    const int tx = t8 & 15, ty = t8 >> 4;
    const int n0 = bi * 32;
    float* Asg = sm + g * 1152;
    float* Wsg = sm + 2304 + g * 640;
    float* P   = sm + 3584;
    const float* W = g_Whh_e + (size_t)n0 * Hh + g * 512;

    for (int t = 0; t < Tt; t++) {
        const float* hcur = (t & 1) ? g_hB : g_hA;
        float*       hnxt = (t & 1) ? g_hA : g_hB;
        const float* Ab = hcur + g * 512;

        unsigned long long acc[2][2] = {{0ull, 0ull}, {0ull, 0ull}};
        for (int k0 = 0; k0 < 512; k0 += 16) {
            load_tiles(Asg, Wsg, Ab, W, k0, t8);
            __syncthreads();
            fma_tile(Asg, Wsg, acc, tx, ty);
            __syncthreads();
        }
        store_partials(P + g * 2048, acc, tx, ty);
        __syncthreads();

        {
            int b = tid >> 3, jj = tid & 7, j = bi * 8 + jj;
            float4 x4 = *(const float4*)(g_enc_xw + ((size_t)b * Tt + t) * G4 + n0 + 4 * jj);
            int base = b * 32 + 4 * jj;
            float vi = P[base + 0] + P[2048 + base + 0] + x4.x;
            float vf = P[base + 1] + P[2048 + base + 1] + x4.y;
            float vg = P[base + 2] + P[2048 + base + 2] + x4.z;
            float vo = P[base + 3] + P[2048 + base + 3] + x4.w;
            float cn = sigm(vf) * g_c1[b * Hh + j] + sigm(vi) * tanhf(vg);
            float hn = sigm(vo) * tanhf(cn);
            g_c1[b * Hh + j] = cn;
            hnxt[b * Hh + j] = hn;
            g_hts[((size_t)b * Tt + t) * Hh + j] = hn;
        }
        gbar();
    }
}

// ================= persistent decoder scan: 3 barriers/step =====================
__global__ __launch_bounds__(512)
void dec_scan(const float* __restrict__ Wc, const float* __restrict__ bc,
              float* __restrict__ scores, float* __restrict__ aw_out)
{
    __shared__ __align__(16) float sm[7680];
    const int tid = threadIdx.x, bi = blockIdx.x;
    const int warp = tid >> 5, lane = tid & 31;
    const int g = tid >> 8, t8 = tid & 255;
    const int tx = t8 & 15, ty = t8 >> 4;
    const int b2 = bi >> 1;
    const int n0 = bi * 32;

    for (int t = 0; t < Tt; t++) {
        const float* h2cur = (t & 1) ? g_h2B : g_h2A;
        float*       h2nxt = (t & 1) ? g_h2A : g_h2B;

        // ---- A: logits + classifier(t-1) ----
        {
            float* sh = sm;
            *(float2*)(sh + tid * 2) = *(const float2*)(h2cur + (size_t)b2 * Hh + tid * 2);
            __syncthreads();
            int th = (bi & 1) * 64;
#pragma unroll
            for (int ii = 0; ii < 4; ii++) {
                int tp = th + ii * 16 + warp;
                const float* pr = g_proj + ((size_t)b2 * Tt + tp) * Hh;
                float s = 0.f;
#pragma unroll 8
                for (int k = lane; k < Hh; k += 32) s += sh[k] * pr[k];
                s = wred(s);
                if (lane == 0) g_logits[b2 * Tt + tp] = s * 0.03125f;
            }
            if (t > 0 && warp < 11) {
                int c = (bi & 1) * 11 + warp;
                const float* w = Wc + (size_t)c * Hh;
                float s = 0.f;
#pragma unroll 8
                for (int k = lane; k < Hh; k += 32) s += sh[k] * w[k];
                s = wred(s);
                if (lane == 0)
                    scores[((size_t)b2 * Tt + (t - 1)) * Cc + c] = s + bc[c];
            }
        }
        gbar();

        // ---- B: softmax + attn context ----
        {
            float* sl = sm;
            float* red = sm + 128;
            if (tid < 128) { float v = g_logits[b2 * Tt + tid]; sl[tid] = v; red[tid] = v; }
            __syncthreads();
            for (int s = 64; s; s >>= 1) {
                if (tid < s) red[tid] = fmaxf(red[tid], red[tid + s]);
                __syncthreads();
            }
            float mx = red[0]; __syncthreads();
            float e = 0.f;
            if (tid < 128) { e = expf(sl[tid] - mx); red[tid] = e; }
            __syncthreads();
            for (int s = 64; s; s >>= 1) {
                if (tid < s) red[tid] += red[tid + s];
                __syncthreads();
            }
            float inv = 1.f / red[0]; __syncthreads();
            if (tid < 128) sl[tid] = e * inv;
            __syncthreads();
            if (t == Tt - 1 && (bi & 1) == 0 && tid < 128)
                aw_out[(size_t)b2 * Tt + tid] = sl[tid];

            int k = (bi & 1) * 512 + tid;
            const float* pb = g_proj + (size_t)b2 * Tt * Hh + k;
            float a = 0.f;
#pragma unroll 4
            for (int tp = 0; tp < Tt; tp++) a = fmaf(sl[tp], pb[(size_t)tp * Hh], a);
            g_attn[(size_t)b2 * Hh + k] = a;
        }
        gbar();

        // ---- C: gates = xw[t] + bf + attn@Wfused^T + h2@Whh_d^T, fused cell ----
        {
            float* Asg = sm + g * 1152;
            float* Wsg = sm + 2304 + g * 640;
            float* P   = sm + 3584;
            const float* Ab = g ? h2cur : g_attn;
            const float* W  = (g ? g_Whh_d : g_Wfused) + (size_t)n0 * Hh;

            unsigned long long acc[2][2] = {{0ull, 0ull}, {0ull, 0ull}};
            for (int k0 = 0; k0 < Hh; k0 += 16) {
                load_tiles(Asg, Wsg, Ab, W, k0, t8);
                __syncthreads();
                fma_tile(Asg, Wsg, acc, tx, ty);
                __syncthreads();
            }
            store_partials(P + g * 2048, acc, tx, ty);
            __syncthreads();

            int b = tid >> 3, jj = tid & 7, j = bi * 8 + jj;
            float4 x4 = *(const float4*)(g_dec_xw + ((size_t)b * Tt + t) * G4 + n0 + 4 * jj);
            float4 bf4 = *(const float4*)(g_bf + n0 + 4 * jj);
            int base = b * 32 + 4 * jj;
            float vi = P[base + 0] + P[2048 + base + 0] + x4.x + bf4.x;
            float vf = P[base + 1] + P[2048 + base + 1] + x4.y + bf4.y;
            float vg = P[base + 2] + P[2048 + base + 2] + x4.z + bf4.z;
            float vo = P[base + 3] + P[2048 + base + 3] + x4.w + bf4.w;
            float cn = sigm(vf) * g_c2[b * Hh + j] + sigm(vi) * tanhf(vg);
            float hn = sigm(vo) * tanhf(cn);
            g_c2[b * Hh + j] = cn;
            h2nxt[b * Hh + j] = hn;
        }
        gbar();
    }

    // ---- final classifier for t = Tt-1 ----
    {
        float* sh = sm;
        *(float2*)(sh + tid * 2) = *(const float2*)(g_h2A + (size_t)b2 * Hh + tid * 2);
        __syncthreads();
        if (warp < 11) {
            int c = (bi & 1) * 11 + warp;
            const float* w = Wc + (size_t)c * Hh;
            float s = 0.f;
#pragma unroll 8
            for (int k = lane; k < Hh; k += 32) s += sh[k] * w[k];
            s = wred(s);
            if (lane == 0)
                scores[((size_t)b2 * Tt + (Tt - 1)) * Cc + c] = s + bc[c];
        }
    }
}

// ---------------- host ----------------
extern "C" void kernel_launch(void* const* d_in, const int* in_sizes, int n_in,
                              void* d_out, int out_size)
{
    const float* x        = (const float*)d_in[0];
    const float* enc_Wih  = (const float*)d_in[1];
    const float* enc_Whh  = (const float*)d_in[2];
    const float* enc_bih  = (const float*)d_in[3];
    const float* enc_bhh  = (const float*)d_in[4];
    const float* We2d     = (const float*)d_in[5];
    const float* be2d     = (const float*)d_in[6];
    const float* Wd2e     = (const float*)d_in[7];
    const float* bd2e     = (const float*)d_in[8];
    const float* dec_Wih  = (const float*)d_in[9];
    const float* dec_Whh  = (const float*)d_in[10];
    const float* dec_bih  = (const float*)d_in[11];
    const float* dec_bhh  = (const float*)d_in[12];
    const float* Wc       = (const float*)d_in[13];
    const float* bc       = (const float*)d_in[14];

    float* out    = (float*)d_out;
    float* scores = out;
    float* aw_out = out + (size_t)Bb * Tt * Cc;

    float *enc_xw_p, *dec_xw_p, *hts_p, *proj_p, *Wih_e_p, *Wih_d_p,
          *Wd_h_p, *Whh_e_p, *Whh_d_p, *Wfused_p, *be_p, *bd_p;
    __nv_bfloat16 *xhi_p, *xlo_p, *Wehi_p, *Welo_p, *Wdhi_p, *Wdlo_p,
                  *htshi_p, *htslo_p, *We2dhi_p, *We2dlo_p;
    cudaGetSymbolAddress((void**)&enc_xw_p, g_enc_xw);
    cudaGetSymbolAddress((void**)&dec_xw_p, g_dec_xw);
    cudaGetSymbolAddress((void**)&hts_p,    g_hts);
    cudaGetSymbolAddress((void**)&proj_p,   g_proj);
    cudaGetSymbolAddress((void**)&Wih_e_p,  g_Wih_e);
    cudaGetSymbolAddress((void**)&Wih_d_p,  g_Wih_d);
    cudaGetSymbolAddress((void**)&Wd_h_p,   g_Wd_h);
    cudaGetSymbolAddress((void**)&Whh_e_p,  g_Whh_e);
    cudaGetSymbolAddress((void**)&Whh_d_p,  g_Whh_d);
    cudaGetSymbolAddress((void**)&Wfused_p, g_Wfused);
    cudaGetSymbolAddress((void**)&be_p,     g_be);
    cudaGetSymbolAddress((void**)&bd_p,     g_bd);
    cudaGetSymbolAddress((void**)&xhi_p,    g_xhi);
    cudaGetSymbolAddress((void**)&xlo_p,    g_xlo);
    cudaGetSymbolAddress((void**)&Wehi_p,   g_Wehi);
    cudaGetSymbolAddress((void**)&Welo_p,   g_Welo);
    cudaGetSymbolAddress((void**)&Wdhi_p,   g_Wdhi);
    cudaGetSymbolAddress((void**)&Wdlo_p,   g_Wdlo);
    cudaGetSymbolAddress((void**)&htshi_p,  g_htshi);
    cudaGetSymbolAddress((void**)&htslo_p,  g_htslo);
    cudaGetSymbolAddress((void**)&We2dhi_p, g_We2dhi);
    cudaGetSymbolAddress((void**)&We2dlo_p, g_We2dlo);

    cudaFuncSetAttribute(mma_gemm, cudaFuncAttributeMaxDynamicSharedMemorySize,
                         MM_SMEM);

    // 1) zero states + barrier
    zero_kernel<<<(Bb * Hh + 255) / 256, 256>>>();

    // 2) permute weights (gate-interleaved rows)
    perm_w_kernel<<<G4, 256>>>(Wih_e_p, enc_Wih, Ff, Ff);
    perm_w_kernel<<<G4, 256>>>(Wih_d_p, dec_Wih, Ff + Hh, Ff);
    perm_w_kernel<<<G4, 256>>>(Whh_e_p, enc_Whh, Hh, Hh);
    perm_w_kernel<<<G4, 256>>>(Wd_h_p,  dec_Wih + Ff, Ff + Hh, Hh);
    perm_w_kernel<<<G4, 256>>>(Whh_d_p, dec_Whh, Hh, Hh);
    perm_b_kernel<<<16, 256>>>(enc_bih, enc_bhh, dec_bih, dec_bhh);
    bfused_kernel<<<G4, 32>>>(bd2e);

    // 3) bf16 hi/lo conversions for TC operands
    {
        int n4;
        n4 = (MT * Ff) / 4;
        conv_hilo<<<(n4 + 255) / 256, 256>>>(x, xhi_p, xlo_p, n4);
        n4 = (G4 * Ff) / 4;
        conv_hilo<<<(n4 + 255) / 256, 256>>>(Wih_e_p, Wehi_p, Welo_p, n4);
        conv_hilo<<<(n4 + 255) / 256, 256>>>(Wih_d_p, Wdhi_p, Wdlo_p, n4);
        n4 = (Hh * Hh) / 4;
        conv_hilo<<<(n4 + 255) / 256, 256>>>(We2d, We2dhi_p, We2dlo_p, n4);
    }

    // 4) Wfused = Wd_h' @ Wd2e (SIMT, small)
    {
        dim3 grid(Hh / 64, G4 / 128);
        gemm128x64_nn<<<grid, 256>>>(Wd_h_p, Hh, Wd2e, Hh, Wfused_p, Hh, Hh);
    }

    // 5) tensor-core pre-GEMMs: enc_xw / dec_xw
    {
        dim3 grid(G4 / 64, MT / 128);
        mma_gemm<<<grid, 256, MM_SMEM>>>(xhi_p, xlo_p, Wehi_p, Welo_p,
                                         be_p, enc_xw_p, G4, Ff);
        mma_gemm<<<grid, 256, MM_SMEM>>>(xhi_p, xlo_p, Wdhi_p, Wdlo_p,
                                         bd_p, dec_xw_p, G4, Ff);
    }

    // 6) encoder scan
    enc_scan<<<NB, 512>>>();

    // 7) convert hts, tensor-core projection
    {
        int n4 = (MT * Hh) / 4;
        conv_hilo<<<(n4 + 255) / 256, 256>>>(hts_p, htshi_p, htslo_p, n4);
        dim3 grid(Hh / 64, MT / 128);
        mma_gemm<<<grid, 256, MM_SMEM>>>(htshi_p, htslo_p, We2dhi_p, We2dlo_p,
                                         be2d, proj_p, Hh, Hh);
    }

    // 8) decoder scan
    dec_scan<<<NB, 512>>>(Wc, bc, scores, aw_out);
}

// round 8
// speedup vs baseline: 3.7072x; 1.8438x over previous
#include <cuda_runtime.h>
#include <cuda_bf16.h>
#include <math.h>
#include <stdint.h>

// Problem dims (fixed)
#define Bb 64
#define Tt 128
#define Ff 2048
#define Hh 1024
#define Cc 22
#define G4 4096   // 4*H
#define NB 128    // persistent grid size
#define MT 8192   // Bb*Tt

// ---------------- scratch (device globals) ----------------
__device__ float g_enc_xw[(size_t)MT*G4];
__device__ float g_dec_xw[(size_t)MT*G4];
__device__ float g_proj[(size_t)MT*Hh];
__device__ float g_c1[Bb*Hh], g_c2[Bb*Hh];
__device__ float g_h2f[2][Bb*Hh];                       // decoder h (fp32, for logits/classifier)
__device__ __nv_bfloat16 g_hhi[2][Bb*Hh], g_hlo[2][Bb*Hh];     // encoder h hi/lo ping-pong
__device__ __nv_bfloat16 g_h2hi[2][Bb*Hh], g_h2lo[2][Bb*Hh];   // decoder h hi/lo ping-pong
__device__ __nv_bfloat16 g_attnhi[Bb*Hh], g_attnlo[Bb*Hh];
__device__ float g_logits[Bb*Tt];
// permuted fp32 weights (row r = g*H+j  ->  p = 4*j+g)
__device__ float g_Wih_e[(size_t)G4*Ff];
__device__ float g_Wih_d[(size_t)G4*Ff];
__device__ float g_Whh_e[(size_t)G4*Hh];
__device__ float g_Wd_h [(size_t)G4*Hh];
__device__ float g_Whh_d[(size_t)G4*Hh];
__device__ float g_Wfused[(size_t)G4*Hh];
__device__ float g_be[G4], g_bd[G4], g_bf[G4];
__device__ unsigned g_barcnt, g_bargen;
// bf16 hi/lo operands for tensor-core GEMMs
__device__ __nv_bfloat16 g_xhi[(size_t)MT*Ff],  g_xlo[(size_t)MT*Ff];
__device__ __nv_bfloat16 g_Wehi[(size_t)G4*Ff], g_Welo[(size_t)G4*Ff];
__device__ __nv_bfloat16 g_Wdhi[(size_t)G4*Ff], g_Wdlo[(size_t)G4*Ff];
__device__ __nv_bfloat16 g_htshi[(size_t)MT*Hh], g_htslo[(size_t)MT*Hh];
__device__ __nv_bfloat16 g_We2dhi[(size_t)Hh*Hh], g_We2dlo[(size_t)Hh*Hh];
__device__ __nv_bfloat16 g_Whhehi[(size_t)G4*Hh], g_Whhelo[(size_t)G4*Hh];
__device__ __nv_bfloat16 g_Wfhi[(size_t)G4*Hh],   g_Wflo[(size_t)G4*Hh];
__device__ __nv_bfloat16 g_Whhdhi[(size_t)G4*Hh], g_Whhdlo[(size_t)G4*Hh];

// ---------------- f32x2 packed helpers (for Wfused SIMT GEMM) ----------------
__device__ __forceinline__ unsigned long long pk2(float x, float y)
{ unsigned long long r; asm("mov.b64 %0, {%1, %2};" : "=l"(r) : "f"(x), "f"(y)); return r; }
__device__ __forceinline__ unsigned long long ffma2(unsigned long long a, unsigned long long b, unsigned long long c)
{ unsigned long long d; asm("fma.rn.f32x2 %0, %1, %2, %3;" : "=l"(d) : "l"(a), "l"(b), "l"(c)); return d; }
__device__ __forceinline__ float2 upk(unsigned long long v)
{ float2 f; asm("mov.b64 {%0, %1}, %2;" : "=f"(f.x), "=f"(f.y) : "l"(v)); return f; }

__device__ __forceinline__ uint32_t smem_u32(const void* p)
{
    uint32_t a;
    asm("{ .reg .u64 t; cvta.to.shared.u64 t, %1; cvt.u32.u64 %0, t; }" : "=r"(a) : "l"(p));
    return a;
}

// ---------------- mma.sync helpers (sm_80+ portable) ----------------
__device__ __forceinline__ void ldmx4(uint32_t* r, uint32_t addr)
{
    asm volatile("ldmatrix.sync.aligned.m8n8.x4.shared.b16 {%0,%1,%2,%3}, [%4];"
        : "=r"(r[0]), "=r"(r[1]), "=r"(r[2]), "=r"(r[3]) : "r"(addr));
}
__device__ __forceinline__ void ldmx2(uint32_t* r, uint32_t addr)
{
    asm volatile("ldmatrix.sync.aligned.m8n8.x2.shared.b16 {%0,%1}, [%2];"
        : "=r"(r[0]), "=r"(r[1]) : "r"(addr));
}
__device__ __forceinline__ void mma16816(float* c, const uint32_t* a, uint32_t b0, uint32_t b1)
{
    asm volatile(
        "mma.sync.aligned.m16n8k16.row.col.f32.bf16.bf16.f32 "
        "{%0,%1,%2,%3}, {%4,%5,%6,%7}, {%8,%9}, {%0,%1,%2,%3};"
        : "+f"(c[0]), "+f"(c[1]), "+f"(c[2]), "+f"(c[3])
        : "r"(a[0]), "r"(a[1]), "r"(a[2]), "r"(a[3]), "r"(b0), "r"(b1));
}
__device__ __forceinline__ void cpa16(uint32_t d, const void* s)
{
    asm volatile("cp.async.cg.shared.global [%0], [%1], 16;" :: "r"(d), "l"(s));
}

// ---------------- grid barrier ----------------
__device__ __forceinline__ void gbar()
{
    __syncthreads();
    if (threadIdx.x == 0) {
        __threadfence();
        unsigned gen = *(volatile unsigned*)&g_bargen;
        if (atomicAdd(&g_barcnt, 1u) == NB - 1u) {
            g_barcnt = 0u;
            __threadfence();
            atomicAdd(&g_bargen, 1u);
        } else {
            while (*(volatile unsigned*)&g_bargen == gen) { }
        }
        __threadfence();
    }
    __syncthreads();
}

__device__ __forceinline__ float sigm(float x) { return 1.f / (1.f + expf(-x)); }
__device__ __forceinline__ float wred(float s)
{
#pragma unroll
    for (int o = 16; o; o >>= 1) s += __shfl_down_sync(0xffffffffu, s, o);
    return s;
}

// ================= setup kernels =================
__global__ void perm_w_kernel(float* dst, const float* src, int ldsrc, int K)
{
    int r = blockIdx.x;
    int g = r >> 10, j = r & 1023;
    int p = 4 * j + g;
    const float* s = src + (size_t)r * ldsrc;
    float*       d = dst + (size_t)p * K;
    for (int k = threadIdx.x * 4; k < K; k += blockDim.x * 4)
        *(float4*)(d + k) = *(const float4*)(s + k);
}

__global__ void perm_b_kernel(const float* ebi, const float* ebh,
                              const float* dbi, const float* dbh)
{
    int r = blockIdx.x * blockDim.x + threadIdx.x;
    if (r < G4) {
        int g = r >> 10, j = r & 1023, p = 4 * j + g;
        g_be[p] = ebi[r] + ebh[r];
        g_bd[p] = dbi[r] + dbh[r];
    }
}

__global__ void bfused_kernel(const float* __restrict__ bd2e)
{
    int p = blockIdx.x;
    const float* w = g_Wd_h + (size_t)p * Hh;
    float s = 0.f;
    for (int k = threadIdx.x; k < Hh; k += 32) s += w[k] * bd2e[k];
    s = wred(s);
    if (threadIdx.x == 0) g_bf[p] = s;
}

__global__ void zero_kernel()
{
    int i = blockIdx.x * blockDim.x + threadIdx.x;
    if (i < Bb * Hh) {
        g_c1[i] = 0.f; g_c2[i] = 0.f;
        g_h2f[0][i] = 0.f; g_h2f[1][i] = 0.f;
        __nv_bfloat16 z = __float2bfloat16(0.f);
        g_hhi[0][i] = z; g_hlo[0][i] = z;
        g_hhi[1][i] = z; g_hlo[1][i] = z;
        g_h2hi[0][i] = z; g_h2lo[0][i] = z;
        g_h2hi[1][i] = z; g_h2lo[1][i] = z;
    }
    if (i == 0) g_barcnt = 0u;
}

// fp32 -> bf16 hi + bf16 lo (lo = bf16(x - hi))
__global__ void conv_hilo(const float* __restrict__ in, __nv_bfloat16* __restrict__ hi,
                          __nv_bfloat16* __restrict__ lo, int n4)
{
    int i = blockIdx.x * blockDim.x + threadIdx.x;
    if (i < n4) {
        float4 v = ((const float4*)in)[i];
        __nv_bfloat162 h01, h23, l01, l23;
        h01.x = __float2bfloat16(v.x); h01.y = __float2bfloat16(v.y);
        h23.x = __float2bfloat16(v.z); h23.y = __float2bfloat16(v.w);
        l01.x = __float2bfloat16(v.x - __bfloat162float(h01.x));
        l01.y = __float2bfloat16(v.y - __bfloat162float(h01.y));
        l23.x = __float2bfloat16(v.z - __bfloat162float(h23.x));
        l23.y = __float2bfloat16(v.w - __bfloat162float(h23.y));
        ((__nv_bfloat162*)hi)[i * 2]     = h01;
        ((__nv_bfloat162*)hi)[i * 2 + 1] = h23;
        ((__nv_bfloat162*)lo)[i * 2]     = l01;
        ((__nv_bfloat162*)lo)[i * 2 + 1] = l23;
    }
}

// ================= mma.sync bf16 split-precision GEMM (pre-GEMMs, projection) ====
#define PADE 40
#define ST_A   (128 * PADE * 2)
#define ST_B   (64 * PADE * 2)
#define STAGE  (2 * ST_A + 2 * ST_B)
#define MM_SMEM (2 * STAGE)

__global__ __launch_bounds__(256)
void mma_gemm(const __nv_bfloat16* __restrict__ Ahi, const __nv_bfloat16* __restrict__ Alo,
              const __nv_bfloat16* __restrict__ Bhi, const __nv_bfloat16* __restrict__ Blo,
              const float* __restrict__ bias, float* __restrict__ C, int ldc, int K)
{
    extern __shared__ char smem[];
    const uint32_t sb = smem_u32(smem);
    const int tid = threadIdx.x;
    const int wid = tid >> 5, lane = tid & 31;
    const int wm = wid & 3, wn = wid >> 2;
    const int m0 = blockIdx.y * 128, n0 = blockIdx.x * 64;

    float acc[2][4][4];
#pragma unroll
    for (int i = 0; i < 2; i++)
#pragma unroll
        for (int j = 0; j < 4; j++)
#pragma unroll
            for (int q = 0; q < 4; q++) acc[i][j][q] = 0.f;

    const int arow = tid >> 2, aseg = tid & 3;
    const int brow = tid >> 2, bseg = tid & 3;
    const int S = K >> 5;
    const int lmat = lane >> 3, lr = lane & 7;
    const uint32_t a_off0 = (uint32_t)(((wm * 32 + (lmat & 1) * 8 + lr) * PADE + (lmat >> 1) * 8) * 2);
    const uint32_t b_off0 = (uint32_t)(((wn * 32 + (lmat & 1) * 8 + lr) * PADE + (lmat >> 1) * 8) * 2);

#define LOAD_STAGE(buf, kb)                                                        \
    do {                                                                           \
        uint32_t st = sb + (buf) * STAGE;                                          \
        const __nv_bfloat16* gAh = Ahi + (size_t)(m0 + arow) * K + (kb) + aseg * 8;\
        const __nv_bfloat16* gAl = Alo + (size_t)(m0 + arow) * K + (kb) + aseg * 8;\
        uint32_t dA = st + (arow * PADE + aseg * 8) * 2;                           \
        cpa16(dA, gAh);                                                            \
        cpa16(dA + ST_A, gAl);                                                     \
        cpa16(dA + 64 * PADE * 2, gAh + (size_t)64 * K);                           \
        cpa16(dA + ST_A + 64 * PADE * 2, gAl + (size_t)64 * K);                    \
        const __nv_bfloat16* gBh = Bhi + (size_t)(n0 + brow) * K + (kb) + bseg * 8;\
        const __nv_bfloat16* gBl = Blo + (size_t)(n0 + brow) * K + (kb) + bseg * 8;\
        uint32_t dB = st + 2 * ST_A + (brow * PADE + bseg * 8) * 2;                \
        cpa16(dB, gBh);                                                            \
        cpa16(dB + ST_B, gBl);                                                     \
    } while (0)

    LOAD_STAGE(0, 0);
    asm volatile("cp.async.commit_group;");

    for (int s = 0; s < S; s++) {
        if (s + 1 < S) {
            LOAD_STAGE((s + 1) & 1, (s + 1) * 32);
            asm volatile("cp.async.commit_group;");
            asm volatile("cp.async.wait_group 1;");
        } else {
            asm volatile("cp.async.wait_group 0;");
        }
        __syncthreads();

        const uint32_t st = sb + (s & 1) * STAGE;
#pragma unroll
        for (int kk = 0; kk < 2; kk++) {
            const uint32_t kadd = (uint32_t)(kk * 16 * 2);
            uint32_t ah[2][4], al[2][4];
#pragma unroll
            for (int mf = 0; mf < 2; mf++) {
                uint32_t aaddr = st + a_off0 + (uint32_t)(mf * 16 * PADE * 2) + kadd;
                ldmx4(ah[mf], aaddr);
                ldmx4(al[mf], aaddr + ST_A);
            }
            uint32_t bh[2][4], bl[2][4];
#pragma unroll
            for (int nf2 = 0; nf2 < 2; nf2++) {
                uint32_t baddr = st + 2 * ST_A + b_off0 + (uint32_t)(nf2 * 16 * PADE * 2) + kadd;
                ldmx4(bh[nf2], baddr);
                ldmx4(bl[nf2], baddr + ST_B);
            }
#pragma unroll
            for (int mf = 0; mf < 2; mf++)
#pragma unroll
                for (int nf2 = 0; nf2 < 2; nf2++) {
                    mma16816(acc[mf][nf2 * 2 + 0], ah[mf], bh[nf2][0], bh[nf2][2]);
                    mma16816(acc[mf][nf2 * 2 + 0], ah[mf], bl[nf2][0], bl[nf2][2]);
                    mma16816(acc[mf][nf2 * 2 + 0], al[mf], bh[nf2][0], bh[nf2][2]);
                    mma16816(acc[mf][nf2 * 2 + 1], ah[mf], bh[nf2][1], bh[nf2][3]);
                    mma16816(acc[mf][nf2 * 2 + 1], ah[mf], bl[nf2][1], bl[nf2][3]);
                    mma16816(acc[mf][nf2 * 2 + 1], al[mf], bh[nf2][1], bh[nf2][3]);
                }
        }
        __syncthreads();
    }

    const int mrow = m0 + wm * 32 + (lane >> 2);
    const int ncol = n0 + wn * 32 + (lane & 3) * 2;
#pragma unroll
    for (int mf = 0; mf < 2; mf++)
#pragma unroll
        for (int nf = 0; nf < 4; nf++) {
            int r = mrow + mf * 16;
            int c = ncol + nf * 8;
            float2 b2 = *(const float2*)(bias + c);
            *(float2*)(C + (size_t)r * ldc + c) =
                make_float2(acc[mf][nf][0] + b2.x, acc[mf][nf][1] + b2.y);
            *(float2*)(C + (size_t)(r + 8) * ldc + c) =
                make_float2(acc[mf][nf][2] + b2.x, acc[mf][nf][3] + b2.y);
        }
#undef LOAD_STAGE
}

// ================= SIMT GEMM (Wfused = Wd_h' @ Wd2e only) =======================
__global__ __launch_bounds__(256)
void gemm128x64_nn(const float* __restrict__ A, int lda,
                   const float* __restrict__ B, int ldb,
                   float* __restrict__ C, int ldc, int K)
{
    __shared__ __align__(16) float As[16][136];
    __shared__ __align__(16) float Bs[16][72];

    const int tid = threadIdx.x;
    const int m0 = blockIdx.y * 128;
    const int n0 = blockIdx.x * 64;
    const int tx = tid & 15;
    const int ty = tid >> 4;

    unsigned long long acc[4][4];
#pragma unroll
    for (int p = 0; p < 4; p++)
#pragma unroll
        for (int j = 0; j < 4; j++) acc[p][j] = 0ull;

    for (int k0 = 0; k0 < K; k0 += 16) {
        {
            int lr = tid >> 1, lc = (tid & 1) * 8;
            const float* a = A + (size_t)(m0 + lr) * lda + k0 + lc;
            float4 v0 = *(const float4*)a;
            float4 v1 = *(const float4*)(a + 4);
            As[lc + 0][lr] = v0.x; As[lc + 1][lr] = v0.y;
            As[lc + 2][lr] = v0.z; As[lc + 3][lr] = v0.w;
            As[lc + 4][lr] = v1.x; As[lc + 5][lr] = v1.y;
            As[lc + 6][lr] = v1.z; As[lc + 7][lr] = v1.w;
        }
        {
            int kr = tid >> 4, nc = (tid & 15) * 4;
            *(float4*)&Bs[kr][nc] = *(const float4*)(B + (size_t)(k0 + kr) * ldb + n0 + nc);
        }
        __syncthreads();
#pragma unroll
        for (int kk = 0; kk < 16; kk++) {
            ulonglong2 ua = *(const ulonglong2*)(&As[kk][ty * 8]);
            ulonglong2 ub = *(const ulonglong2*)(&As[kk][ty * 8 + 4]);
            float4 w = *(const float4*)(&Bs[kk][tx * 4]);
            unsigned long long w0 = pk2(w.x, w.x), w1 = pk2(w.y, w.y);
            unsigned long long w2 = pk2(w.z, w.z), w3 = pk2(w.w, w.w);
            acc[0][0] = ffma2(ua.x, w0, acc[0][0]); acc[0][1] = ffma2(ua.x, w1, acc[0][1]);
            acc[0][2] = ffma2(ua.x, w2, acc[0][2]); acc[0][3] = ffma2(ua.x, w3, acc[0][3]);
            acc[1][0] = ffma2(ua.y, w0, acc[1][0]); acc[1][1] = ffma2(ua.y, w1, acc[1][1]);
            acc[1][2] = ffma2(ua.y, w2, acc[1][2]); acc[1][3] = ffma2(ua.y, w3, acc[1][3]);
            acc[2][0] = ffma2(ub.x, w0, acc[2][0]); acc[2][1] = ffma2(ub.x, w1, acc[2][1]);
            acc[2][2] = ffma2(ub.x, w2, acc[2][2]); acc[2][3] = ffma2(ub.x, w3, acc[2][3]);
            acc[3][0] = ffma2(ub.y, w0, acc[3][0]); acc[3][1] = ffma2(ub.y, w1, acc[3][1]);
            acc[3][2] = ffma2(ub.y, w2, acc[3][2]); acc[3][3] = ffma2(ub.y, w3, acc[3][3]);
        }
        __syncthreads();
    }

#pragma unroll
    for (int p = 0; p < 4; p++) {
        float2 f0 = upk(acc[p][0]), f1 = upk(acc[p][1]);
        float2 f2 = upk(acc[p][2]), f3 = upk(acc[p][3]);
        int m = m0 + ty * 8 + 2 * p;
        *(float4*)(C + (size_t)m * ldc + n0 + tx * 4) = make_float4(f0.x, f1.x, f2.x, f3.x);
        *(float4*)(C + (size_t)(m + 1) * ldc + n0 + tx * 4) = make_float4(f0.y, f1.y, f2.y, f3.y);
    }
}

// ================= persistent encoder scan (mma-based, 1 barrier/step) ==========
// smem: stage[2] of { Ahi[64][72], Alo, Whi[32][72], Wlo } + P[64][32] fp32
#define EKC 64
#define EPITCH 144                 // bytes per smem row (72 bf16)
#define E_A_PL (64 * EPITCH)       // 9216
#define E_W_PL (32 * EPITCH)       // 4608
#define E_STAGE (2 * E_A_PL + 2 * E_W_PL)   // 27648
#define E_SMEM  (2 * E_STAGE + 8192)        // 63488

__global__ __launch_bounds__(512)
void enc_scan()
{
    extern __shared__ char smc[];
    const uint32_t sb = smem_u32(smc);
    const int tid = threadIdx.x, bi = blockIdx.x;
    const int wid = tid >> 5, lane = tid & 31;
    const int wm = wid & 3, wn = wid >> 2;    // 4 m-tiles x 4 n-tiles(8)
    const int n0 = bi * 32;
    const int lmat = lane >> 3, lr = lane & 7;
    const uint32_t a_loff = (uint32_t)((wm * 16 + (lmat & 1) * 8 + lr) * EPITCH + (lmat >> 1) * 16);
    const uint32_t b_loff = (uint32_t)((wn * 8 + (lane & 7)) * EPITCH + ((lane & 15) >> 3) * 16);
    float* P = (float*)(smc + 2 * E_STAGE);
    // per-thread load slots
    const int ar = tid >> 3, asg = tid & 7;              // A: 64 rows x 8 segs
    const int wpl = tid >> 8, wr = (tid >> 3) & 31, wsg = tid & 7;  // W: plane, 32 rows

#define E_LOAD(bf, kc) do {                                                       \
    uint32_t st = sb + (bf) * E_STAGE;                                            \
    int kcc = (kc) * EKC;                                                         \
    cpa16(st + ar * EPITCH + asg * 16,          Ahi + ar * Hh + kcc + asg * 8);   \
    cpa16(st + E_A_PL + ar * EPITCH + asg * 16, Alo + ar * Hh + kcc + asg * 8);   \
    const __nv_bfloat16* ws = wpl ? g_Whhelo : g_Whhehi;                          \
    cpa16(st + 2 * E_A_PL + wpl * E_W_PL + wr * EPITCH + wsg * 16,                \
          ws + (size_t)(n0 + wr) * Hh + kcc + wsg * 8);                           \
} while (0)

    for (int t = 0; t < Tt; t++) {
        const __nv_bfloat16* Ahi = g_hhi[t & 1];
        const __nv_bfloat16* Alo = g_hlo[t & 1];

        float acc[4] = {0.f, 0.f, 0.f, 0.f};
        E_LOAD(0, 0);
        asm volatile("cp.async.commit_group;");
        for (int kc = 0; kc < 16; kc++) {
            if (kc < 15) {
                E_LOAD((kc + 1) & 1, kc + 1);
                asm volatile("cp.async.commit_group;");
                asm volatile("cp.async.wait_group 1;");
            } else {
                asm volatile("cp.async.wait_group 0;");
            }
            __syncthreads();
            uint32_t st = sb + (kc & 1) * E_STAGE;
#pragma unroll
            for (int kk = 0; kk < 4; kk++) {
                uint32_t ka = (uint32_t)(kk * 32);
                uint32_t ahi[4], alo[4], bh[2], bl[2];
                ldmx4(ahi, st + a_loff + ka);
                ldmx4(alo, st + E_A_PL + a_loff + ka);
                ldmx2(bh, st + 2 * E_A_PL + b_loff + ka);
                ldmx2(bl, st + 2 * E_A_PL + E_W_PL + b_loff + ka);
                mma16816(acc, ahi, bh[0], bh[1]);
                mma16816(acc, ahi, bl[0], bl[1]);
                mma16816(acc, alo, bh[0], bh[1]);
            }
            __syncthreads();
        }
        {   // store partials (each warp owns a distinct 16x8 region)
            int row = wm * 16 + (lane >> 2), col = wn * 8 + (lane & 3) * 2;
            P[row * 32 + col] = acc[0];       P[row * 32 + col + 1] = acc[1];
            P[(row + 8) * 32 + col] = acc[2]; P[(row + 8) * 32 + col + 1] = acc[3];
        }
        __syncthreads();
        {   // fused LSTM cell
            int b = tid >> 3, jj = tid & 7, j = bi * 8 + jj;
            float4 x4 = *(const float4*)(g_enc_xw + ((size_t)b * Tt + t) * G4 + n0 + 4 * jj);
            int base = b * 32 + 4 * jj;
            float vi = P[base + 0] + x4.x;
            float vf = P[base + 1] + x4.y;
            float vg = P[base + 2] + x4.z;
            float vo = P[base + 3] + x4.w;
            float cn = sigm(vf) * g_c1[b * Hh + j] + sigm(vi) * tanhf(vg);
            float hn = sigm(vo) * tanhf(cn);
            g_c1[b * Hh + j] = cn;
            __nv_bfloat16 hh = __float2bfloat16(hn);
            __nv_bfloat16 hl = __float2bfloat16(hn - __bfloat162float(hh));
            g_hhi[(t + 1) & 1][b * Hh + j] = hh;
            g_hlo[(t + 1) & 1][b * Hh + j] = hl;
            g_htshi[((size_t)b * Tt + t) * Hh + j] = hh;
            g_htslo[((size_t)b * Tt + t) * Hh + j] = hl;
        }
        gbar();
    }
#undef E_LOAD
}

// ================= persistent decoder scan (mma-based, 3 barriers/step) =========
// smem: stage[2] of { Attn hi/lo [64][72], H2 hi/lo [64][72], Wf hi/lo [32][72],
//                     Whh hi/lo [32][72] } + P[2][64][32] fp32
#define D_A_PL (64 * EPITCH)       // 9216
#define D_W_PL (32 * EPITCH)       // 4608
#define D_STAGE (4 * D_A_PL + 4 * D_W_PL)   // 55296
#define D_SMEM  (2 * D_STAGE + 16384)       // 126976

__global__ __launch_bounds__(512)
void dec_scan(const float* __restrict__ Wc, const float* __restrict__ bc,
              float* __restrict__ scores, float* __restrict__ aw_out)
{
    extern __shared__ char smc[];
    const uint32_t sb = smem_u32(smc);
    float* sm = (float*)smc;
    const int tid = threadIdx.x, bi = blockIdx.x;
    const int wid = tid >> 5, lane = tid & 31;
    const int warp = wid;
    const int b2 = bi >> 1;
    const int n0 = bi * 32;
    // phase C warp mapping: 2 groups x (4 m-tiles x 2 n-tiles(16))
    const int grp = wid >> 3, wg = wid & 7;
    const int wm = wg & 3, wn = wg >> 2;
    const int lmat = lane >> 3, lr = lane & 7;
    const uint32_t a_loff = (uint32_t)((wm * 16 + (lmat & 1) * 8 + lr) * EPITCH + (lmat >> 1) * 16)
                          + (uint32_t)(grp * 2 * D_A_PL);
    const uint32_t b_loff = (uint32_t)((wn * 16 + (lmat & 1) * 8 + lr) * EPITCH + (lmat >> 1) * 16)
                          + (uint32_t)(4 * D_A_PL + grp * 2 * D_W_PL);
    float* P = (float*)(smc + 2 * D_STAGE);
    const int ar = tid >> 3, asg = tid & 7;
    const int wpl = tid >> 8, wr = (tid >> 3) & 31, wsg = tid & 7;

#define D_LOAD(bf, kc) do {                                                       \
    uint32_t st = sb + (bf) * D_STAGE;                                            \
    int kcc = (kc) * EKC;                                                         \
    cpa16(st + 0 * D_A_PL + ar * EPITCH + asg * 16, g_attnhi + ar * Hh + kcc + asg * 8); \
    cpa16(st + 1 * D_A_PL + ar * EPITCH + asg * 16, g_attnlo + ar * Hh + kcc + asg * 8); \
    cpa16(st + 2 * D_A_PL + ar * EPITCH + asg * 16, h2hi + ar * Hh + kcc + asg * 8);     \
    cpa16(st + 3 * D_A_PL + ar * EPITCH + asg * 16, h2lo + ar * Hh + kcc + asg * 8);     \
    const __nv_bfloat16* w0s = wpl ? g_Wflo : g_Wfhi;                             \
    cpa16(st + 4 * D_A_PL + wpl * D_W_PL + wr * EPITCH + wsg * 16,                \
          w0s + (size_t)(n0 + wr) * Hh + kcc + wsg * 8);                          \
    const __nv_bfloat16* w1s = wpl ? g_Whhdlo : g_Whhdhi;                         \
    cpa16(st + 4 * D_A_PL + (2 + wpl) * D_W_PL + wr * EPITCH + wsg * 16,          \
          w1s + (size_t)(n0 + wr) * Hh + kcc + wsg * 8);                          \
} while (0)

    for (int t = 0; t < Tt; t++) {
        const float* h2cur = g_h2f[t & 1];

        // ---- A: logits + classifier(t-1) ----
        {
            float* sh = sm;
            *(float2*)(sh + tid * 2) = *(const float2*)(h2cur + (size_t)b2 * Hh + tid * 2);
            __syncthreads();
            int th = (bi & 1) * 64;
#pragma unroll
            for (int ii = 0; ii < 4; ii++) {
                int tp = th + ii * 16 + warp;
                const float* pr = g_proj + ((size_t)b2 * Tt + tp) * Hh;
                float s = 0.f;
#pragma unroll 8
                for (int k = lane; k < Hh; k += 32) s += sh[k] * pr[k];
                s = wred(s);
                if (lane == 0) g_logits[b2 * Tt + tp] = s * 0.03125f;
            }
            if (t > 0 && warp < 11) {
                int c = (bi & 1) * 11 + warp;
                const float* w = Wc + (size_t)c * Hh;
                float s = 0.f;
#pragma unroll 8
                for (int k = lane; k < Hh; k += 32) s += sh[k] * w[k];
                s = wred(s);
                if (lane == 0)
                    scores[((size_t)b2 * Tt + (t - 1)) * Cc + c] = s + bc[c];
            }
        }
        gbar();

        // ---- B: softmax + attn context (writes bf16 hi/lo) ----
        {
            float* sl = sm;
            float* red = sm + 128;
            if (tid < 128) { float v = g_logits[b2 * Tt + tid]; sl[tid] = v; red[tid] = v; }
            __syncthreads();
            for (int s = 64; s; s >>= 1) {
                if (tid < s) red[tid] = fmaxf(red[tid], red[tid + s]);
                __syncthreads();
            }
            float mx = red[0]; __syncthreads();
            float e = 0.f;
            if (tid < 128) { e = expf(sl[tid] - mx); red[tid] = e; }
            __syncthreads();
            for (int s = 64; s; s >>= 1) {
                if (tid < s) red[tid] += red[tid + s];
                __syncthreads();
            }
            float inv = 1.f / red[0]; __syncthreads();
            if (tid < 128) sl[tid] = e * inv;
            __syncthreads();
            if (t == Tt - 1 && (bi & 1) == 0 && tid < 128)
                aw_out[(size_t)b2 * Tt + tid] = sl[tid];

            int k = (bi & 1) * 512 + tid;
            const float* pb = g_proj + (size_t)b2 * Tt * Hh + k;
            float a = 0.f;
#pragma unroll 4
            for (int tp = 0; tp < Tt; tp++) a = fmaf(sl[tp], pb[(size_t)tp * Hh], a);
            __nv_bfloat16 ah = __float2bfloat16(a);
            g_attnhi[(size_t)b2 * Hh + k] = ah;
            g_attnlo[(size_t)b2 * Hh + k] = __float2bfloat16(a - __bfloat162float(ah));
        }
        gbar();

        // ---- C: gates = xw[t] + bf + attn@Wfused^T + h2@Whh_d^T (mma), cell ----
        {
            const __nv_bfloat16* h2hi = g_h2hi[t & 1];
            const __nv_bfloat16* h2lo = g_h2lo[t & 1];

            float acc0[4] = {0.f, 0.f, 0.f, 0.f};
            float acc1[4] = {0.f, 0.f, 0.f, 0.f};
            D_LOAD(0, 0);
            asm volatile("cp.async.commit_group;");
            for (int kc = 0; kc < 16; kc++) {
                if (kc < 15) {
                    D_LOAD((kc + 1) & 1, kc + 1);
                    asm volatile("cp.async.commit_group;");
                    asm volatile("cp.async.wait_group 1;");
                } else {
                    asm volatile("cp.async.wait_group 0;");
                }
                __syncthreads();
                uint32_t st = sb + (kc & 1) * D_STAGE;
#pragma unroll
                for (int kk = 0; kk < 4; kk++) {
                    uint32_t ka = (uint32_t)(kk * 32);
                    uint32_t ahi[4], alo[4], bhv[4], blv[4];
                    ldmx4(ahi, st + a_loff + ka);
                    ldmx4(alo, st + a_loff + D_A_PL + ka);
                    ldmx4(bhv, st + b_loff + ka);
                    ldmx4(blv, st + b_loff + D_W_PL + ka);
                    mma16816(acc0, ahi, bhv[0], bhv[2]);
                    mma16816(acc0, ahi, blv[0], blv[2]);
                    mma16816(acc0, alo, bhv[0], bhv[2]);
                    mma16816(acc1, ahi, bhv[1], bhv[3]);
                    mma16816(acc1, ahi, blv[1], blv[3]);
                    mma16816(acc1, alo, bhv[1], bhv[3]);
                }
                __syncthreads();
            }
            {   // store partials: group grp, 16x16 region per warp
                float* Pg = P + grp * 2048;
                int row = wm * 16 + (lane >> 2), col = wn * 16 + (lane & 3) * 2;
                Pg[row * 32 + col] = acc0[0];       Pg[row * 32 + col + 1] = acc0[1];
                Pg[(row + 8) * 32 + col] = acc0[2]; Pg[(row + 8) * 32 + col + 1] = acc0[3];
                Pg[row * 32 + col + 8] = acc1[0];       Pg[row * 32 + col + 9] = acc1[1];
                Pg[(row + 8) * 32 + col + 8] = acc1[2]; Pg[(row + 8) * 32 + col + 9] = acc1[3];
            }
            __syncthreads();
            {   // fused LSTM cell
                int b = tid >> 3, jj = tid & 7, j = bi * 8 + jj;
                float4 x4 = *(const float4*)(g_dec_xw + ((size_t)b * Tt + t) * G4 + n0 + 4 * jj);
                float4 bf4 = *(const float4*)(g_bf + n0 + 4 * jj);
                int base = b * 32 + 4 * jj;
                float vi = P[base + 0] + P[2048 + base + 0] + x4.x + bf4.x;
                float vf = P[base + 1] + P[2048 + base + 1] + x4.y + bf4.y;
                float vg = P[base + 2] + P[2048 + base + 2] + x4.z + bf4.z;
                float vo = P[base + 3] + P[2048 + base + 3] + x4.w + bf4.w;
                float cn = sigm(vf) * g_c2[b * Hh + j] + sigm(vi) * tanhf(vg);
                float hn = sigm(vo) * tanhf(cn);
                g_c2[b * Hh + j] = cn;
                g_h2f[(t + 1) & 1][b * Hh + j] = hn;
                __nv_bfloat16 hh = __float2bfloat16(hn);
                g_h2hi[(t + 1) & 1][b * Hh + j] = hh;
                g_h2lo[(t + 1) & 1][b * Hh + j] = __float2bfloat16(hn - __bfloat162float(hh));
            }
        }
        gbar();
    }

    // ---- final classifier for t = Tt-1 (h2 in fp32 buffer 0 after t=127) ----
    {
        float* sh = sm;
        *(float2*)(sh + tid * 2) = *(const float2*)(g_h2f[0] + (size_t)b2 * Hh + tid * 2);
        __syncthreads();
        if (warp < 11) {
            int c = (bi & 1) * 11 + warp;
            const float* w = Wc + (size_t)c * Hh;
            float s = 0.f;
#pragma unroll 8
            for (int k = lane; k < Hh; k += 32) s += sh[k] * w[k];
            s = wred(s);
            if (lane == 0)
                scores[((size_t)b2 * Tt + (Tt - 1)) * Cc + c] = s + bc[c];
        }
    }
#undef D_LOAD
}

// ---------------- host ----------------
extern "C" void kernel_launch(void* const* d_in, const int* in_sizes, int n_in,
                              void* d_out, int out_size)
{
    const float* x        = (const float*)d_in[0];
    const float* enc_Wih  = (const float*)d_in[1];
    const float* enc_Whh  = (const float*)d_in[2];
    const float* enc_bih  = (const float*)d_in[3];
    const float* enc_bhh  = (const float*)d_in[4];
    const float* We2d     = (const float*)d_in[5];
    const float* be2d     = (const float*)d_in[6];
    const float* Wd2e     = (const float*)d_in[7];
    const float* bd2e     = (const float*)d_in[8];
    const float* dec_Wih  = (const float*)d_in[9];
    const float* dec_Whh  = (const float*)d_in[10];
    const float* dec_bih  = (const float*)d_in[11];
    const float* dec_bhh  = (const float*)d_in[12];
    const float* Wc       = (const float*)d_in[13];
    const float* bc       = (const float*)d_in[14];

    float* out    = (float*)d_out;
    float* scores = out;
    float* aw_out = out + (size_t)Bb * Tt * Cc;

    float *enc_xw_p, *dec_xw_p, *proj_p, *Wih_e_p, *Wih_d_p,
          *Wd_h_p, *Whh_e_p, *Whh_d_p, *Wfused_p, *be_p, *bd_p;
    __nv_bfloat16 *xhi_p, *xlo_p, *Wehi_p, *Welo_p, *Wdhi_p, *Wdlo_p,
                  *htshi_p, *htslo_p, *We2dhi_p, *We2dlo_p,
                  *Whhehi_p, *Whhelo_p, *Wfhi_p, *Wflo_p, *Whhdhi_p, *Whhdlo_p;
    cudaGetSymbolAddress((void**)&enc_xw_p, g_enc_xw);
    cudaGetSymbolAddress((void**)&dec_xw_p, g_dec_xw);
    cudaGetSymbolAddress((void**)&proj_p,   g_proj);
    cudaGetSymbolAddress((void**)&Wih_e_p,  g_Wih_e);
    cudaGetSymbolAddress((void**)&Wih_d_p,  g_Wih_d);
    cudaGetSymbolAddress((void**)&Wd_h_p,   g_Wd_h);
    cudaGetSymbolAddress((void**)&Whh_e_p,  g_Whh_e);
    cudaGetSymbolAddress((void**)&Whh_d_p,  g_Whh_d);
    cudaGetSymbolAddress((void**)&Wfused_p, g_Wfused);
    cudaGetSymbolAddress((void**)&be_p,     g_be);
    cudaGetSymbolAddress((void**)&bd_p,     g_bd);
    cudaGetSymbolAddress((void**)&xhi_p,    g_xhi);
    cudaGetSymbolAddress((void**)&xlo_p,    g_xlo);
    cudaGetSymbolAddress((void**)&Wehi_p,   g_Wehi);
    cudaGetSymbolAddress((void**)&Welo_p,   g_Welo);
    cudaGetSymbolAddress((void**)&Wdhi_p,   g_Wdhi);
    cudaGetSymbolAddress((void**)&Wdlo_p,   g_Wdlo);
    cudaGetSymbolAddress((void**)&htshi_p,  g_htshi);
    cudaGetSymbolAddress((void**)&htslo_p,  g_htslo);
    cudaGetSymbolAddress((void**)&We2dhi_p, g_We2dhi);
    cudaGetSymbolAddress((void**)&We2dlo_p, g_We2dlo);
    cudaGetSymbolAddress((void**)&Whhehi_p, g_Whhehi);
    cudaGetSymbolAddress((void**)&Whhelo_p, g_Whhelo);
    cudaGetSymbolAddress((void**)&Wfhi_p,   g_Wfhi);
    cudaGetSymbolAddress((void**)&Wflo_p,   g_Wflo);
    cudaGetSymbolAddress((void**)&Whhdhi_p, g_Whhdhi);
    cudaGetSymbolAddress((void**)&Whhdlo_p, g_Whhdlo);

    cudaFuncSetAttribute(mma_gemm, cudaFuncAttributeMaxDynamicSharedMemorySize, MM_SMEM);
    cudaFuncSetAttribute(enc_scan, cudaFuncAttributeMaxDynamicSharedMemorySize, E_SMEM);
    cudaFuncSetAttribute(dec_scan, cudaFuncAttributeMaxDynamicSharedMemorySize, D_SMEM);

    // 1) zero states + barrier
    zero_kernel<<<(Bb * Hh + 255) / 256, 256>>>();

    // 2) permute weights (gate-interleaved rows)
    perm_w_kernel<<<G4, 256>>>(Wih_e_p, enc_Wih, Ff, Ff);
    perm_w_kernel<<<G4, 256>>>(Wih_d_p, dec_Wih, Ff + Hh, Ff);
    perm_w_kernel<<<G4, 256>>>(Whh_e_p, enc_Whh, Hh, Hh);
    perm_w_kernel<<<G4, 256>>>(Wd_h_p,  dec_Wih + Ff, Ff + Hh, Hh);
    perm_w_kernel<<<G4, 256>>>(Whh_d_p, dec_Whh, Hh, Hh);
    perm_b_kernel<<<16, 256>>>(enc_bih, enc_bhh, dec_bih, dec_bhh);
    bfused_kernel<<<G4, 32>>>(bd2e);

    // 3) bf16 hi/lo conversions
    {
        int n4;
        n4 = (MT * Ff) / 4;
        conv_hilo<<<(n4 + 255) / 256, 256>>>(x, xhi_p, xlo_p, n4);
        n4 = (G4 * Ff) / 4;
        conv_hilo<<<(n4 + 255) / 256, 256>>>(Wih_e_p, Wehi_p, Welo_p, n4);
        conv_hilo<<<(n4 + 255) / 256, 256>>>(Wih_d_p, Wdhi_p, Wdlo_p, n4);
        n4 = (Hh * Hh) / 4;
        conv_hilo<<<(n4 + 255) / 256, 256>>>(We2d, We2dhi_p, We2dlo_p, n4);
        n4 = (G4 * Hh) / 4;
        conv_hilo<<<(n4 + 255) / 256, 256>>>(Whh_e_p, Whhehi_p, Whhelo_p, n4);
        conv_hilo<<<(n4 + 255) / 256, 256>>>(Whh_d_p, Whhdhi_p, Whhdlo_p, n4);
    }

    // 4) Wfused = Wd_h' @ Wd2e (SIMT, small) + its hi/lo conversion
    {
        dim3 grid(Hh / 64, G4 / 128);
        gemm128x64_nn<<<grid, 256>>>(Wd_h_p, Hh, Wd2e, Hh, Wfused_p, Hh, Hh);
        int n4 = (G4 * Hh) / 4;
        conv_hilo<<<(n4 + 255) / 256, 256>>>(Wfused_p, Wfhi_p, Wflo_p, n4);
    }

    // 5) tensor-core pre-GEMMs: enc_xw / dec_xw
    {
        dim3 grid(G4 / 64, MT / 128);
        mma_gemm<<<grid, 256, MM_SMEM>>>(xhi_p, xlo_p, Wehi_p, Welo_p,
                                         be_p, enc_xw_p, G4, Ff);
        mma_gemm<<<grid, 256, MM_SMEM>>>(xhi_p, xlo_p, Wdhi_p, Wdlo_p,
                                         bd_p, dec_xw_p, G4, Ff);
    }

    // 6) encoder scan (mma-based; emits hts hi/lo directly)
    enc_scan<<<NB, 512, E_SMEM>>>();

    // 7) tensor-core projection (consumes hts hi/lo)
    {
        dim3 grid(Hh / 64, MT / 128);
        mma_gemm<<<grid, 256, MM_SMEM>>>(htshi_p, htslo_p, We2dhi_p, We2dlo_p,
                                         be2d, proj_p, Hh, Hh);
    }

    // 8) decoder scan (mma-based)
    dec_scan<<<NB, 512, D_SMEM>>>(Wc, bc, scores, aw_out);
}